// round 9
// baseline (speedup 1.0000x reference)
#include <cuda_runtime.h>
#include <cuda_fp16.h>
#include <cstdint>

#define NN 50000
#define EE 800000
#define HD 128
#define ODIM 40
#define PAD 96

// ---------------- scratch (static __device__, no allocations) ----------------
__device__ __align__(16) __half g_hh[NN * HD];   // GEMM outputs fp16 (40-wide reuse for L3)
__device__ __align__(16) __half g_x[NN * HD];    // input x fp16
__device__ __align__(16) __half g_a[NN * HD];    // post-agg activations fp16
__device__ __align__(16) __half g_w0h[HD * HD];
__device__ __align__(16) __half g_w1h[HD * HD];
__device__ __align__(16) __half g_w2h[ODIM * HD];
__device__ float g_dinv[NN];
__device__ int   g_cnt[NN];
__device__ __align__(16) int g_ell[NN * PAD];    // ELL: src indices per dst
__device__ int   g_is64;

// ======================= edge-index dtype detection =======================
__device__ __forceinline__ int load_edge(const void* ei, int idx) {
    if (g_is64) return (int)((const long long*)ei)[idx];
    return ((const int*)ei)[idx];
}

// ======================= init: zero counts + dtype detect =======================
__global__ void k_init(const void* ei, int n) {
    int i = blockIdx.x * blockDim.x + threadIdx.x;
    if (i < n) g_cnt[i] = 0;
    if (blockIdx.x == 0) {
        __shared__ int any;
        if (threadIdx.x == 0) any = 0;
        __syncthreads();
        const int* p = (const int*)ei;
        for (int j = threadIdx.x; j < 512; j += blockDim.x)
            if (p[2 * j + 1] != 0) any = 1;
        __syncthreads();
        if (threadIdx.x == 0) g_is64 = any ? 0 : 1;
    }
}

// ======================= fill: direct ELL scatter (no hist/prefix needed) =======================
__global__ void k_fill(const void* ei, int E) {
    int e = blockIdx.x * blockDim.x + threadIdx.x;
    if (e >= E) return;
    int s = load_edge(ei, e);
    int d = load_edge(ei, E + e);
    int pos = atomicAdd(&g_cnt[d], 1);
    if (pos < PAD) g_ell[d * PAD + pos] = s;
}

// ======================= prep: x -> fp16, W transpose/quantize, dinv =======================
__global__ void k_prep(const float* __restrict__ x, const float* __restrict__ W0,
                       const float* __restrict__ W1, const float* __restrict__ W2,
                       int total4, int n)
{
    int i = blockIdx.x * blockDim.x + threadIdx.x;
    if (i < total4) {
        float4 v = ((const float4*)x)[i];
        __half2* ph = (__half2*)&g_x[(size_t)i * 4];
        ph[0] = __halves2half2(__float2half_rn(v.x), __float2half_rn(v.y));
        ph[1] = __halves2half2(__float2half_rn(v.z), __float2half_rn(v.w));
        return;
    }
    int j = i - total4;
    if (j < 16384) {
        g_w0h[j] = __float2half_rn(W0[(j & 127) * 128 + (j >> 7)]);
    } else if (j < 32768) {
        int k = j - 16384;
        g_w1h[k] = __float2half_rn(W1[(k & 127) * 128 + (k >> 7)]);
    } else if (j < 32768 + ODIM * 128) {
        int k = j - 32768;
        int nn = k >> 7, kk = k & 127;
        g_w2h[k] = __float2half_rn(W2[kk * ODIM + nn]);
    } else {
        int k = j - (32768 + ODIM * 128);
        if (k < n) g_dinv[k] = rsqrtf((float)(g_cnt[k] + 1));
    }
}

// ======================= mma.sync fp16 GEMM =======================
__device__ __forceinline__ void mma_f16(float* c, uint32_t a0, uint32_t a1,
                                        uint32_t a2, uint32_t a3,
                                        uint32_t b0, uint32_t b1) {
    asm volatile(
        "mma.sync.aligned.m16n8k16.row.col.f32.f16.f16.f32 "
        "{%0,%1,%2,%3}, {%4,%5,%6,%7}, {%8,%9}, {%0,%1,%2,%3};"
        : "+f"(c[0]), "+f"(c[1]), "+f"(c[2]), "+f"(c[3])
        : "r"(a0), "r"(a1), "r"(a2), "r"(a3), "r"(b0), "r"(b1));
}

// [n,128] @ W[K=128,128] -> [n,128] fp16 (fp32 accum).
// CTA tile 64 x 128, 8 warps (4 M x 2 N), warp tile 16 x 64, NT=8.
__global__ void __launch_bounds__(256) k_gemm128(
    const __half* __restrict__ A, const __half* __restrict__ Bh,
    __half* __restrict__ Out, int n)
{
    constexpr int NT = 8;
    constexpr int BS = 136;
    __shared__ __half sB[HD * BS];

    int tid = threadIdx.x, wid = tid >> 5, lane = tid & 31;
    int widM = wid & 3, widN = wid >> 2;
    int grp = lane >> 2;
    int qid = lane & 3;
    int rowA = blockIdx.x * 64 + widM * 16 + grp;
    int rowB = rowA + 8;
    bool okA = rowA < n, okB = rowB < n;
    int ncol0 = widN * 64;

#pragma unroll
    for (int it = 0; it < 8; it++) {
        int i = it * 256 + tid;
        int r = i >> 4, ck = i & 15;
        *(int4*)&sB[r * BS + ck * 8] = *(const int4*)&Bh[(size_t)r * 128 + ck * 8];
    }
    __syncthreads();

    float acc[NT][4];
#pragma unroll
    for (int t = 0; t < NT; t++)
#pragma unroll
        for (int j = 0; j < 4; j++) acc[t][j] = 0.f;

    const size_t offA = (size_t)rowA * 128 + qid * 2;
    const size_t offB = (size_t)rowB * 128 + qid * 2;

#pragma unroll
    for (int k0 = 0; k0 < 128; k0 += 16) {
        uint32_t a0 = 0, a1 = 0, a2 = 0, a3 = 0;
        if (okA) {
            a0 = *(const uint32_t*)&A[offA + k0];
            a2 = *(const uint32_t*)&A[offA + k0 + 8];
        }
        if (okB) {
            a1 = *(const uint32_t*)&A[offB + k0];
            a3 = *(const uint32_t*)&A[offB + k0 + 8];
        }
#pragma unroll
        for (int t = 0; t < NT; t++) {
            const __half* bp = &sB[(ncol0 + t * 8 + grp) * BS + k0 + qid * 2];
            uint32_t b0 = *(const uint32_t*)bp;
            uint32_t b1 = *(const uint32_t*)(bp + 8);
            mma_f16(acc[t], a0, a1, a2, a3, b0, b1);
        }
    }

#pragma unroll
    for (int t = 0; t < NT; t++) {
        int col = ncol0 + t * 8 + qid * 2;
        if (okA) *(__half2*)&Out[(size_t)rowA * 128 + col] = __floats2half2_rn(acc[t][0], acc[t][1]);
        if (okB) *(__half2*)&Out[(size_t)rowB * 128 + col] = __floats2half2_rn(acc[t][2], acc[t][3]);
    }
}

// [n,128] @ W2[K=128,40] -> [n,40] fp16. CTA tile 128 x 40, 8 warps in M, NT=5.
__global__ void __launch_bounds__(256) k_gemm40(
    const __half* __restrict__ A, const __half* __restrict__ Bh,
    __half* __restrict__ Out, int n)
{
    constexpr int NT = ODIM / 8;
    constexpr int BS = 136;
    __shared__ __half sB[ODIM * BS];

    int tid = threadIdx.x, wid = tid >> 5, lane = tid & 31;
    int grp = lane >> 2;
    int qid = lane & 3;
    int rowA = blockIdx.x * 128 + wid * 16 + grp;
    int rowB = rowA + 8;
    bool okA = rowA < n, okB = rowB < n;

    for (int i = tid; i < ODIM * 16; i += 256) {
        int r = i >> 4, ck = i & 15;
        *(int4*)&sB[r * BS + ck * 8] = *(const int4*)&Bh[(size_t)r * 128 + ck * 8];
    }
    __syncthreads();

    float acc[NT][4];
#pragma unroll
    for (int t = 0; t < NT; t++)
#pragma unroll
        for (int j = 0; j < 4; j++) acc[t][j] = 0.f;

    const size_t offA = (size_t)rowA * 128 + qid * 2;
    const size_t offB = (size_t)rowB * 128 + qid * 2;

#pragma unroll
    for (int k0 = 0; k0 < 128; k0 += 16) {
        uint32_t a0 = 0, a1 = 0, a2 = 0, a3 = 0;
        if (okA) {
            a0 = *(const uint32_t*)&A[offA + k0];
            a2 = *(const uint32_t*)&A[offA + k0 + 8];
        }
        if (okB) {
            a1 = *(const uint32_t*)&A[offB + k0];
            a3 = *(const uint32_t*)&A[offB + k0 + 8];
        }
#pragma unroll
        for (int t = 0; t < NT; t++) {
            const __half* bp = &sB[(t * 8 + grp) * BS + k0 + qid * 2];
            uint32_t b0 = *(const uint32_t*)bp;
            uint32_t b1 = *(const uint32_t*)(bp + 8);
            mma_f16(acc[t], a0, a1, a2, a3, b0, b1);
        }
    }

#pragma unroll
    for (int t = 0; t < NT; t++) {
        int col = t * 8 + qid * 2;
        if (okA) *(__half2*)&Out[(size_t)rowA * ODIM + col] = __floats2half2_rn(acc[t][0], acc[t][1]);
        if (okB) *(__half2*)&Out[(size_t)rowB * ODIM + col] = __floats2half2_rn(acc[t][2], acc[t][3]);
    }
}

// ======================= aggregation (128-wide, fp16 gather, dinv-at-gather) =======================
__device__ __forceinline__ float4 ldrow128(const __half* __restrict__ H, int row, int lane) {
    uint2 u = *(const uint2*)&H[(size_t)row * 128 + lane * 4];
    float2 fa = __half22float2(*(__half2*)&u.x);
    float2 fb = __half22float2(*(__half2*)&u.y);
    return make_float4(fa.x, fa.y, fb.x, fb.y);
}

__global__ void __launch_bounds__(256) k_agg128(
    const __half* __restrict__ Hh, const float* __restrict__ b,
    __half* __restrict__ Oh, int n)
{
    int gw = (blockIdx.x * blockDim.x + threadIdx.x) >> 5;
    int lane = threadIdx.x & 31;
    if (gw >= n) return;

    float dd = g_dinv[gw];
    // acc = dinv[d]*h_d (self) + sum dinv[s]*h_s ; final *= dinv[d]
    float4 v = ldrow128(Hh, gw, lane);
    float4 acc = make_float4(v.x * dd, v.y * dd, v.z * dd, v.w * dd);

    const int* ell = &g_ell[gw * PAD];
    int m = min(g_cnt[gw], PAD);
    int e = 0;
    for (; e + 3 < m; e += 4) {
        int4 S = *(const int4*)&ell[e];          // aligned: PAD%4==0
        float w0 = __ldg(&g_dinv[S.x]);
        float w1 = __ldg(&g_dinv[S.y]);
        float w2 = __ldg(&g_dinv[S.z]);
        float w3 = __ldg(&g_dinv[S.w]);
        float4 v0 = ldrow128(Hh, S.x, lane);
        float4 v1 = ldrow128(Hh, S.y, lane);
        float4 v2 = ldrow128(Hh, S.z, lane);
        float4 v3 = ldrow128(Hh, S.w, lane);
        acc.x += w0 * v0.x + w1 * v1.x + w2 * v2.x + w3 * v3.x;
        acc.y += w0 * v0.y + w1 * v1.y + w2 * v2.y + w3 * v3.y;
        acc.z += w0 * v0.z + w1 * v1.z + w2 * v2.z + w3 * v3.z;
        acc.w += w0 * v0.w + w1 * v1.w + w2 * v2.w + w3 * v3.w;
    }
    for (; e < m; e++) {
        int s = __ldg(&ell[e]);
        float w0 = __ldg(&g_dinv[s]);
        float4 v0 = ldrow128(Hh, s, lane);
        acc.x += w0 * v0.x; acc.y += w0 * v0.y;
        acc.z += w0 * v0.z; acc.w += w0 * v0.w;
    }

    float4 bb = *(const float4*)&b[lane * 4];
    acc.x = fmaxf(fmaf(acc.x, dd, bb.x), 0.f);
    acc.y = fmaxf(fmaf(acc.y, dd, bb.y), 0.f);
    acc.z = fmaxf(fmaf(acc.z, dd, bb.z), 0.f);
    acc.w = fmaxf(fmaf(acc.w, dd, bb.w), 0.f);

    __half2* ph = (__half2*)&Oh[(size_t)gw * 128 + lane * 4];
    ph[0] = __floats2half2_rn(acc.x, acc.y);
    ph[1] = __floats2half2_rn(acc.z, acc.w);
}

// ======================= aggregation (40-wide) + bias + ReLU + log_softmax =======================
__global__ void __launch_bounds__(256) k_agg40(
    const __half* __restrict__ H3, const float* __restrict__ b2,
    float* __restrict__ O, int n)
{
    int gw = (blockIdx.x * blockDim.x + threadIdx.x) >> 5;
    int lane = threadIdx.x & 31;
    if (gw >= n) return;

    float dd = g_dinv[gw];
    const __half* hr = &H3[(size_t)gw * ODIM];
    float a1 = dd * __half2float(hr[lane]);
    float a2 = (lane < 8) ? dd * __half2float(hr[32 + lane]) : 0.f;

    const int* ell = &g_ell[gw * PAD];
    int m = min(g_cnt[gw], PAD);
    int e = 0;
    for (; e + 1 < m; e += 2) {
        int s0 = __ldg(&ell[e]);
        int s1 = __ldg(&ell[e + 1]);
        float w0 = __ldg(&g_dinv[s0]);
        float w1 = __ldg(&g_dinv[s1]);
        const __half* r0 = &H3[(size_t)s0 * ODIM];
        const __half* r1 = &H3[(size_t)s1 * ODIM];
        a1 += w0 * __half2float(r0[lane]) + w1 * __half2float(r1[lane]);
        if (lane < 8)
            a2 += w0 * __half2float(r0[32 + lane]) + w1 * __half2float(r1[32 + lane]);
    }
    if (e < m) {
        int s = __ldg(&ell[e]);
        float w = __ldg(&g_dinv[s]);
        const __half* sr = &H3[(size_t)s * ODIM];
        a1 += w * __half2float(sr[lane]);
        if (lane < 8) a2 += w * __half2float(sr[32 + lane]);
    }

    a1 = fmaxf(fmaf(a1, dd, b2[lane]), 0.f);
    if (lane < 8) a2 = fmaxf(fmaf(a2, dd, b2[32 + lane]), 0.f);

    float mx = fmaxf(a1, (lane < 8) ? a2 : -1e30f);
#pragma unroll
    for (int off = 16; off > 0; off >>= 1)
        mx = fmaxf(mx, __shfl_xor_sync(0xFFFFFFFFu, mx, off));

    float s = expf(a1 - mx) + ((lane < 8) ? expf(a2 - mx) : 0.f);
#pragma unroll
    for (int off = 16; off > 0; off >>= 1)
        s += __shfl_xor_sync(0xFFFFFFFFu, s, off);

    float l = mx + logf(s);
    O[(size_t)gw * ODIM + lane] = a1 - l;
    if (lane < 8) O[(size_t)gw * ODIM + 32 + lane] = a2 - l;
}

// ======================= launch =======================
extern "C" void kernel_launch(void* const* d_in, const int* in_sizes, int n_in,
                              void* d_out, int out_size)
{
    const float* x  = (const float*)d_in[0];
    const void*  ei = d_in[1];
    const float* W0 = (const float*)d_in[2];
    const float* b0 = (const float*)d_in[3];
    const float* W1 = (const float*)d_in[4];
    const float* b1 = (const float*)d_in[5];
    const float* W2 = (const float*)d_in[6];
    const float* b2 = (const float*)d_in[7];
    float* out = (float*)d_out;

    int N = in_sizes[0] / HD;
    int E = in_sizes[1] / 2;

    __half *hhP, *xP, *aP, *w0h, *w1h, *w2h;
    cudaGetSymbolAddress((void**)&hhP, g_hh);
    cudaGetSymbolAddress((void**)&xP, g_x);
    cudaGetSymbolAddress((void**)&aP, g_a);
    cudaGetSymbolAddress((void**)&w0h, g_w0h);
    cudaGetSymbolAddress((void**)&w1h, g_w1h);
    cudaGetSymbolAddress((void**)&w2h, g_w2h);

    int tb = 256;
    int nbN = (N + tb - 1) / tb;
    int nbE = (E + tb - 1) / tb;
    int nbWarp = (N * 32 + tb - 1) / tb;
    int nbG64 = (N + 63) / 64;
    int nbG128 = (N + 127) / 128;
    int total4 = N * HD / 4;
    int nbPrep = (total4 + 32768 + ODIM * 128 + N + tb - 1) / tb;

    // idx0: init (zero counts + dtype detect)
    k_init<<<nbN, tb>>>(ei, N);
    // idx1: ELL fill (atomic slot assignment; no hist/prefix)
    k_fill<<<nbE, tb>>>(ei, E);
    // idx2: prep (x fp16 + W quantize/transpose + dinv from counts)
    k_prep<<<nbPrep, tb>>>(x, W0, W1, W2, total4, N);
    // idx3: layer-1 GEMM (ncu capture slot)
    k_gemm128<<<nbG64, 256>>>(xP, w0h, hhP, N);
    k_agg128<<<nbWarp, tb>>>(hhP, b0, aP, N);
    // layer 2
    k_gemm128<<<nbG64, 256>>>(aP, w1h, hhP, N);
    k_agg128<<<nbWarp, tb>>>(hhP, b1, aP, N);
    // layer 3
    k_gemm40<<<nbG128, 256>>>(aP, w2h, hhP, N);
    k_agg40<<<nbWarp, tb>>>(hhP, b2, out, N);
}

// round 10
// speedup vs baseline: 1.5359x; 1.5359x over previous
#include <cuda_runtime.h>
#include <cuda_fp16.h>
#include <cstdint>

#define NN 50000
#define EE 800000
#define HD 128
#define ODIM 40

// ---------------- scratch (static __device__, no allocations) ----------------
__device__ __align__(16) __half g_hh[NN * HD];   // GEMM outputs h' = dinv*h, fp16 (40-wide reuse L3)
__device__ __align__(16) __half g_x[NN * HD];    // input x fp16
__device__ __align__(16) __half g_a[NN * HD];    // post-agg activations fp16
__device__ __align__(16) __half g_w0h[HD * HD];
__device__ __align__(16) __half g_w1h[HD * HD];
__device__ __align__(16) __half g_w2h[ODIM * HD];
__device__ float g_dinv[NN];
__device__ int   g_cnt[NN];
__device__ int   g_rowptr[NN];
__device__ int   g_cursor[NN];
__device__ int   g_esrc[EE];                     // CSR: src index per edge (4B records)
__device__ int   g_total;
__device__ int   g_is64;

// ======================= edge-index dtype detection =======================
__device__ __forceinline__ int load_edge(const void* ei, int idx) {
    if (g_is64) return (int)((const long long*)ei)[idx];
    return ((const int*)ei)[idx];
}

// ======================= CSR build =======================
__global__ void k_init(const void* ei, int n) {
    int i = blockIdx.x * blockDim.x + threadIdx.x;
    if (i < n) g_cnt[i] = 0;
    if (i == 0) g_total = 0;
    if (blockIdx.x == 0) {
        __shared__ int any;
        if (threadIdx.x == 0) any = 0;
        __syncthreads();
        const int* p = (const int*)ei;
        for (int j = threadIdx.x; j < 512; j += blockDim.x)
            if (p[2 * j + 1] != 0) any = 1;
        __syncthreads();
        if (threadIdx.x == 0) g_is64 = any ? 0 : 1;
    }
}

__global__ void k_hist(const void* ei, int E) {
    int e = blockIdx.x * blockDim.x + threadIdx.x;
    if (e >= E) return;
    atomicAdd(&g_cnt[load_edge(ei, E + e)], 1);
}

// unordered segment assignment (order irrelevant: fill uses cursors, agg uses rowptr+cnt)
__global__ void k_rowptr(int n) {
    int i = blockIdx.x * blockDim.x + threadIdx.x;
    if (i >= n) return;
    int c = g_cnt[i];
    g_dinv[i] = rsqrtf((float)(c + 1));
    int pos = atomicAdd(&g_total, c);
    g_rowptr[i] = pos;
    g_cursor[i] = pos;
}

__global__ void k_fill(const void* ei, int E) {
    int e = blockIdx.x * blockDim.x + threadIdx.x;
    if (e >= E) return;
    int s = load_edge(ei, e);
    int d = load_edge(ei, E + e);
    int pos = atomicAdd(&g_cursor[d], 1);
    g_esrc[pos] = s;
}

// ======================= prep: x -> fp16 + W transpose/quantize =======================
__global__ void k_prep(const float* __restrict__ x, const float* __restrict__ W0,
                       const float* __restrict__ W1, const float* __restrict__ W2,
                       int total4)
{
    int i = blockIdx.x * blockDim.x + threadIdx.x;
    if (i < total4) {
        float4 v = ((const float4*)x)[i];
        __half2* ph = (__half2*)&g_x[(size_t)i * 4];
        ph[0] = __halves2half2(__float2half_rn(v.x), __float2half_rn(v.y));
        ph[1] = __halves2half2(__float2half_rn(v.z), __float2half_rn(v.w));
    } else {
        int j = i - total4;
        if (j < 16384) {
            g_w0h[j] = __float2half_rn(W0[(j & 127) * 128 + (j >> 7)]);
        } else if (j < 32768) {
            int k = j - 16384;
            g_w1h[k] = __float2half_rn(W1[(k & 127) * 128 + (k >> 7)]);
        } else if (j < 32768 + ODIM * 128) {
            int k = j - 32768;
            int nn = k >> 7, kk = k & 127;
            g_w2h[k] = __float2half_rn(W2[kk * ODIM + nn]);
        }
    }
}

// ======================= mma.sync fp16 GEMM =======================
__device__ __forceinline__ void mma_f16(float* c, uint32_t a0, uint32_t a1,
                                        uint32_t a2, uint32_t a3,
                                        uint32_t b0, uint32_t b1) {
    asm volatile(
        "mma.sync.aligned.m16n8k16.row.col.f32.f16.f16.f32 "
        "{%0,%1,%2,%3}, {%4,%5,%6,%7}, {%8,%9}, {%0,%1,%2,%3};"
        : "+f"(c[0]), "+f"(c[1]), "+f"(c[2]), "+f"(c[3])
        : "r"(a0), "r"(a1), "r"(a2), "r"(a3), "r"(b0), "r"(b1));
}

// [n,128] @ W[K=128,128] -> h' = dinv[row] * (A@W), fp16 out (fp32 accum).
// CTA tile 64 x 128, 8 warps (4 M x 2 N), warp tile 16 x 64, NT=8.
__global__ void __launch_bounds__(256) k_gemm128(
    const __half* __restrict__ A, const __half* __restrict__ Bh,
    __half* __restrict__ Out, int n)
{
    constexpr int NT = 8;
    constexpr int BS = 136;
    __shared__ __half sB[HD * BS];

    int tid = threadIdx.x, wid = tid >> 5, lane = tid & 31;
    int widM = wid & 3, widN = wid >> 2;
    int grp = lane >> 2;
    int qid = lane & 3;
    int rowA = blockIdx.x * 64 + widM * 16 + grp;
    int rowB = rowA + 8;
    bool okA = rowA < n, okB = rowB < n;
    int ncol0 = widN * 64;

#pragma unroll
    for (int it = 0; it < 8; it++) {
        int i = it * 256 + tid;
        int r = i >> 4, ck = i & 15;
        *(int4*)&sB[r * BS + ck * 8] = *(const int4*)&Bh[(size_t)r * 128 + ck * 8];
    }
    __syncthreads();

    float acc[NT][4];
#pragma unroll
    for (int t = 0; t < NT; t++)
#pragma unroll
        for (int j = 0; j < 4; j++) acc[t][j] = 0.f;

    const size_t offA = (size_t)rowA * 128 + qid * 2;
    const size_t offB = (size_t)rowB * 128 + qid * 2;

#pragma unroll
    for (int k0 = 0; k0 < 128; k0 += 16) {
        uint32_t a0 = 0, a1 = 0, a2 = 0, a3 = 0;
        if (okA) {
            a0 = *(const uint32_t*)&A[offA + k0];
            a2 = *(const uint32_t*)&A[offA + k0 + 8];
        }
        if (okB) {
            a1 = *(const uint32_t*)&A[offB + k0];
            a3 = *(const uint32_t*)&A[offB + k0 + 8];
        }
#pragma unroll
        for (int t = 0; t < NT; t++) {
            const __half* bp = &sB[(ncol0 + t * 8 + grp) * BS + k0 + qid * 2];
            uint32_t b0 = *(const uint32_t*)bp;
            uint32_t b1 = *(const uint32_t*)(bp + 8);
            mma_f16(acc[t], a0, a1, a2, a3, b0, b1);
        }
    }

    float dA = okA ? g_dinv[rowA] : 0.f;
    float dB = okB ? g_dinv[rowB] : 0.f;
#pragma unroll
    for (int t = 0; t < NT; t++) {
        int col = ncol0 + t * 8 + qid * 2;
        if (okA) *(__half2*)&Out[(size_t)rowA * 128 + col] =
            __floats2half2_rn(acc[t][0] * dA, acc[t][1] * dA);
        if (okB) *(__half2*)&Out[(size_t)rowB * 128 + col] =
            __floats2half2_rn(acc[t][2] * dB, acc[t][3] * dB);
    }
}

// [n,128] @ W2[K=128,40] -> dinv-prescaled fp16. CTA tile 128 x 40, 8 warps in M, NT=5.
__global__ void __launch_bounds__(256) k_gemm40(
    const __half* __restrict__ A, const __half* __restrict__ Bh,
    __half* __restrict__ Out, int n)
{
    constexpr int NT = ODIM / 8;
    constexpr int BS = 136;
    __shared__ __half sB[ODIM * BS];

    int tid = threadIdx.x, wid = tid >> 5, lane = tid & 31;
    int grp = lane >> 2;
    int qid = lane & 3;
    int rowA = blockIdx.x * 128 + wid * 16 + grp;
    int rowB = rowA + 8;
    bool okA = rowA < n, okB = rowB < n;

    for (int i = tid; i < ODIM * 16; i += 256) {
        int r = i >> 4, ck = i & 15;
        *(int4*)&sB[r * BS + ck * 8] = *(const int4*)&Bh[(size_t)r * 128 + ck * 8];
    }
    __syncthreads();

    float acc[NT][4];
#pragma unroll
    for (int t = 0; t < NT; t++)
#pragma unroll
        for (int j = 0; j < 4; j++) acc[t][j] = 0.f;

    const size_t offA = (size_t)rowA * 128 + qid * 2;
    const size_t offB = (size_t)rowB * 128 + qid * 2;

#pragma unroll
    for (int k0 = 0; k0 < 128; k0 += 16) {
        uint32_t a0 = 0, a1 = 0, a2 = 0, a3 = 0;
        if (okA) {
            a0 = *(const uint32_t*)&A[offA + k0];
            a2 = *(const uint32_t*)&A[offA + k0 + 8];
        }
        if (okB) {
            a1 = *(const uint32_t*)&A[offB + k0];
            a3 = *(const uint32_t*)&A[offB + k0 + 8];
        }
#pragma unroll
        for (int t = 0; t < NT; t++) {
            const __half* bp = &sB[(t * 8 + grp) * BS + k0 + qid * 2];
            uint32_t b0 = *(const uint32_t*)bp;
            uint32_t b1 = *(const uint32_t*)(bp + 8);
            mma_f16(acc[t], a0, a1, a2, a3, b0, b1);
        }
    }

    float dA = okA ? g_dinv[rowA] : 0.f;
    float dB = okB ? g_dinv[rowB] : 0.f;
#pragma unroll
    for (int t = 0; t < NT; t++) {
        int col = t * 8 + qid * 2;
        if (okA) *(__half2*)&Out[(size_t)rowA * ODIM + col] =
            __floats2half2_rn(acc[t][0] * dA, acc[t][1] * dA);
        if (okB) *(__half2*)&Out[(size_t)rowB * ODIM + col] =
            __floats2half2_rn(acc[t][2] * dB, acc[t][3] * dB);
    }
}

// ======================= aggregation (128-wide): unweighted gather-sum of h' =======================
__device__ __forceinline__ float4 ldrow128(const __half* __restrict__ H, int row, int lane) {
    uint2 u = *(const uint2*)&H[(size_t)row * 128 + lane * 4];
    float2 fa = __half22float2(*(__half2*)&u.x);
    float2 fb = __half22float2(*(__half2*)&u.y);
    return make_float4(fa.x, fa.y, fb.x, fb.y);
}

__global__ void __launch_bounds__(256) k_agg128(
    const __half* __restrict__ Hh, const float* __restrict__ b,
    __half* __restrict__ Oh, int n)
{
    int gw = (blockIdx.x * blockDim.x + threadIdx.x) >> 5;
    int lane = threadIdx.x & 31;
    if (gw >= n) return;

    // out = relu( dinv[d] * (h'_d + sum h'_s) + b ),  h' rows are dinv-prescaled
    float4 acc = ldrow128(Hh, gw, lane);   // self term h'_d

    int beg = g_rowptr[gw];
    int m = g_cnt[gw];
    int e = 0;
    for (; e + 3 < m; e += 4) {
        int s0 = __ldg(&g_esrc[beg + e]);
        int s1 = __ldg(&g_esrc[beg + e + 1]);
        int s2 = __ldg(&g_esrc[beg + e + 2]);
        int s3 = __ldg(&g_esrc[beg + e + 3]);
        float4 v0 = ldrow128(Hh, s0, lane);
        float4 v1 = ldrow128(Hh, s1, lane);
        float4 v2 = ldrow128(Hh, s2, lane);
        float4 v3 = ldrow128(Hh, s3, lane);
        acc.x += v0.x + v1.x + v2.x + v3.x;
        acc.y += v0.y + v1.y + v2.y + v3.y;
        acc.z += v0.z + v1.z + v2.z + v3.z;
        acc.w += v0.w + v1.w + v2.w + v3.w;
    }
    for (; e < m; e++) {
        int s0 = __ldg(&g_esrc[beg + e]);
        float4 v0 = ldrow128(Hh, s0, lane);
        acc.x += v0.x; acc.y += v0.y; acc.z += v0.z; acc.w += v0.w;
    }

    float dd = g_dinv[gw];
    float4 bb = *(const float4*)&b[lane * 4];
    acc.x = fmaxf(fmaf(acc.x, dd, bb.x), 0.f);
    acc.y = fmaxf(fmaf(acc.y, dd, bb.y), 0.f);
    acc.z = fmaxf(fmaf(acc.z, dd, bb.z), 0.f);
    acc.w = fmaxf(fmaf(acc.w, dd, bb.w), 0.f);

    __half2* ph = (__half2*)&Oh[(size_t)gw * 128 + lane * 4];
    ph[0] = __floats2half2_rn(acc.x, acc.y);
    ph[1] = __floats2half2_rn(acc.z, acc.w);
}

// ======================= aggregation (40-wide) + bias + ReLU + log_softmax =======================
__global__ void __launch_bounds__(256) k_agg40(
    const __half* __restrict__ H3, const float* __restrict__ b2,
    float* __restrict__ O, int n)
{
    int gw = (blockIdx.x * blockDim.x + threadIdx.x) >> 5;
    int lane = threadIdx.x & 31;
    if (gw >= n) return;

    const __half* hr = &H3[(size_t)gw * ODIM];
    float a1 = __half2float(hr[lane]);
    float a2 = (lane < 8) ? __half2float(hr[32 + lane]) : 0.f;

    int beg = g_rowptr[gw];
    int m = g_cnt[gw];
    int e = 0;
    for (; e + 1 < m; e += 2) {
        int s0 = __ldg(&g_esrc[beg + e]);
        int s1 = __ldg(&g_esrc[beg + e + 1]);
        const __half* r0 = &H3[(size_t)s0 * ODIM];
        const __half* r1 = &H3[(size_t)s1 * ODIM];
        a1 += __half2float(r0[lane]) + __half2float(r1[lane]);
        if (lane < 8)
            a2 += __half2float(r0[32 + lane]) + __half2float(r1[32 + lane]);
    }
    if (e < m) {
        int s = __ldg(&g_esrc[beg + e]);
        const __half* sr = &H3[(size_t)s * ODIM];
        a1 += __half2float(sr[lane]);
        if (lane < 8) a2 += __half2float(sr[32 + lane]);
    }

    float dd = g_dinv[gw];
    a1 = fmaxf(fmaf(a1, dd, b2[lane]), 0.f);
    if (lane < 8) a2 = fmaxf(fmaf(a2, dd, b2[32 + lane]), 0.f);

    float mx = fmaxf(a1, (lane < 8) ? a2 : -1e30f);
#pragma unroll
    for (int off = 16; off > 0; off >>= 1)
        mx = fmaxf(mx, __shfl_xor_sync(0xFFFFFFFFu, mx, off));

    float s = expf(a1 - mx) + ((lane < 8) ? expf(a2 - mx) : 0.f);
#pragma unroll
    for (int off = 16; off > 0; off >>= 1)
        s += __shfl_xor_sync(0xFFFFFFFFu, s, off);

    float l = mx + logf(s);
    O[(size_t)gw * ODIM + lane] = a1 - l;
    if (lane < 8) O[(size_t)gw * ODIM + 32 + lane] = a2 - l;
}

// ======================= launch =======================
extern "C" void kernel_launch(void* const* d_in, const int* in_sizes, int n_in,
                              void* d_out, int out_size)
{
    const float* x  = (const float*)d_in[0];
    const void*  ei = d_in[1];
    const float* W0 = (const float*)d_in[2];
    const float* b0 = (const float*)d_in[3];
    const float* W1 = (const float*)d_in[4];
    const float* b1 = (const float*)d_in[5];
    const float* W2 = (const float*)d_in[6];
    const float* b2 = (const float*)d_in[7];
    float* out = (float*)d_out;

    int N = in_sizes[0] / HD;
    int E = in_sizes[1] / 2;

    __half *hhP, *xP, *aP, *w0h, *w1h, *w2h;
    cudaGetSymbolAddress((void**)&hhP, g_hh);
    cudaGetSymbolAddress((void**)&xP, g_x);
    cudaGetSymbolAddress((void**)&aP, g_a);
    cudaGetSymbolAddress((void**)&w0h, g_w0h);
    cudaGetSymbolAddress((void**)&w1h, g_w1h);
    cudaGetSymbolAddress((void**)&w2h, g_w2h);

    int tb = 256;
    int nbN = (N + tb - 1) / tb;
    int nbE = (E + tb - 1) / tb;
    int nbWarp = (N * 32 + tb - 1) / tb;
    int nbG64 = (N + 63) / 64;
    int nbG128 = (N + 127) / 128;
    int total4 = N * HD / 4;
    int nbPrep = (total4 + 32768 + ODIM * 128 + tb - 1) / tb;

    // idx0..3: CSR build (k_fill at capture slot 3 — validate 4B-record speedup)
    k_init<<<nbN, tb>>>(ei, N);
    k_hist<<<nbE, tb>>>(ei, E);
    k_rowptr<<<nbN, tb>>>(N);
    k_fill<<<nbE, tb>>>(ei, E);
    // idx4: prep
    k_prep<<<nbPrep, tb>>>(x, W0, W1, W2, total4);
    // layer 1
    k_gemm128<<<nbG64, 256>>>(xP, w0h, hhP, N);
    k_agg128<<<nbWarp, tb>>>(hhP, b0, aP, N);
    // layer 2
    k_gemm128<<<nbG64, 256>>>(aP, w1h, hhP, N);
    k_agg128<<<nbWarp, tb>>>(hhP, b1, aP, N);
    // layer 3
    k_gemm40<<<nbG128, 256>>>(aP, w2h, hhP, N);
    k_agg40<<<nbWarp, tb>>>(hhP, b2, out, N);
}

// round 12
// speedup vs baseline: 1.5684x; 1.0211x over previous
#include <cuda_runtime.h>
#include <cuda_fp16.h>
#include <cstdint>

#define NN 50000
#define EE 800000
#define HD 128
#define ODIM 40

// ---------------- scratch (static __device__, no allocations) ----------------
__device__ __align__(16) __half g_hh[NN * HD];   // GEMM outputs h' = dinv*h, fp16 (40-wide reuse L3)
__device__ __align__(16) __half g_x[NN * HD];    // input x fp16
__device__ __align__(16) __half g_a[NN * HD];    // post-agg activations fp16
__device__ __align__(16) __half g_w0h[HD * HD];
__device__ __align__(16) __half g_w1h[HD * HD];
__device__ __align__(16) __half g_w2h[ODIM * HD];
__device__ float g_dinv[NN];
__device__ int   g_cnt[NN];
__device__ int   g_rowptr[NN];
__device__ int   g_cursor[NN];
__device__ int   g_esrc[EE];                     // CSR: src index per edge (4B records)
__device__ int   g_total;
__device__ int   g_is64;

// ======================= edge-index dtype detection =======================
__device__ __forceinline__ int load_edge(const void* ei, int idx) {
    if (g_is64) return (int)((const long long*)ei)[idx];
    return ((const int*)ei)[idx];
}

// ======================= CSR build =======================
__global__ void k_init(const void* ei, int n) {
    int i = blockIdx.x * blockDim.x + threadIdx.x;
    if (i < n) g_cnt[i] = 0;
    if (i == 0) g_total = 0;
    if (blockIdx.x == 0) {
        __shared__ int any;
        if (threadIdx.x == 0) any = 0;
        __syncthreads();
        const int* p = (const int*)ei;
        for (int j = threadIdx.x; j < 512; j += blockDim.x)
            if (p[2 * j + 1] != 0) any = 1;
        __syncthreads();
        if (threadIdx.x == 0) g_is64 = any ? 0 : 1;
    }
}

__global__ void k_hist(const void* ei, int E) {
    int e = blockIdx.x * blockDim.x + threadIdx.x;
    if (e >= E) return;
    atomicAdd(&g_cnt[load_edge(ei, E + e)], 1);
}

// unordered segment assignment (order irrelevant: fill uses cursors, agg uses rowptr+cnt)
__global__ void k_rowptr(int n) {
    int i = blockIdx.x * blockDim.x + threadIdx.x;
    if (i >= n) return;
    int c = g_cnt[i];
    g_dinv[i] = rsqrtf((float)(c + 1));
    int pos = atomicAdd(&g_total, c);
    g_rowptr[i] = pos;
    g_cursor[i] = pos;
}

__global__ void k_fill(const void* ei, int E) {
    int e = blockIdx.x * blockDim.x + threadIdx.x;
    if (e >= E) return;
    int s = load_edge(ei, e);
    int d = load_edge(ei, E + e);
    int pos = atomicAdd(&g_cursor[d], 1);
    g_esrc[pos] = s;
}

// ======================= prep: x -> fp16 + W transpose/quantize =======================
__global__ void k_prep(const float* __restrict__ x, const float* __restrict__ W0,
                       const float* __restrict__ W1, const float* __restrict__ W2,
                       int total4)
{
    int i = blockIdx.x * blockDim.x + threadIdx.x;
    if (i < total4) {
        float4 v = ((const float4*)x)[i];
        __half2* ph = (__half2*)&g_x[(size_t)i * 4];
        ph[0] = __halves2half2(__float2half_rn(v.x), __float2half_rn(v.y));
        ph[1] = __halves2half2(__float2half_rn(v.z), __float2half_rn(v.w));
    } else {
        int j = i - total4;
        if (j < 16384) {
            g_w0h[j] = __float2half_rn(W0[(j & 127) * 128 + (j >> 7)]);
        } else if (j < 32768) {
            int k = j - 16384;
            g_w1h[k] = __float2half_rn(W1[(k & 127) * 128 + (k >> 7)]);
        } else if (j < 32768 + ODIM * 128) {
            int k = j - 32768;
            int nn = k >> 7, kk = k & 127;
            g_w2h[k] = __float2half_rn(W2[kk * ODIM + nn]);
        }
    }
}

// ======================= mma.sync fp16 GEMM =======================
__device__ __forceinline__ void mma_f16(float* c, uint32_t a0, uint32_t a1,
                                        uint32_t a2, uint32_t a3,
                                        uint32_t b0, uint32_t b1) {
    asm volatile(
        "mma.sync.aligned.m16n8k16.row.col.f32.f16.f16.f32 "
        "{%0,%1,%2,%3}, {%4,%5,%6,%7}, {%8,%9}, {%0,%1,%2,%3};"
        : "+f"(c[0]), "+f"(c[1]), "+f"(c[2]), "+f"(c[3])
        : "r"(a0), "r"(a1), "r"(a2), "r"(a3), "r"(b0), "r"(b1));
}

// [n,128] @ W[K=128,128] -> h' = dinv[row] * (A@W), fp16 out (fp32 accum).
// CTA tile 64 x 128, 8 warps (4 M x 2 N), warp tile 16 x 64, NT=8.
__global__ void __launch_bounds__(256) k_gemm128(
    const __half* __restrict__ A, const __half* __restrict__ Bh,
    __half* __restrict__ Out, int n)
{
    constexpr int NT = 8;
    constexpr int BS = 136;
    __shared__ __half sB[HD * BS];

    int tid = threadIdx.x, wid = tid >> 5, lane = tid & 31;
    int widM = wid & 3, widN = wid >> 2;
    int grp = lane >> 2;
    int qid = lane & 3;
    int rowA = blockIdx.x * 64 + widM * 16 + grp;
    int rowB = rowA + 8;
    bool okA = rowA < n, okB = rowB < n;
    int ncol0 = widN * 64;

#pragma unroll
    for (int it = 0; it < 8; it++) {
        int i = it * 256 + tid;
        int r = i >> 4, ck = i & 15;
        *(int4*)&sB[r * BS + ck * 8] = *(const int4*)&Bh[(size_t)r * 128 + ck * 8];
    }
    __syncthreads();

    float acc[NT][4];
#pragma unroll
    for (int t = 0; t < NT; t++)
#pragma unroll
        for (int j = 0; j < 4; j++) acc[t][j] = 0.f;

    const size_t offA = (size_t)rowA * 128 + qid * 2;
    const size_t offB = (size_t)rowB * 128 + qid * 2;

#pragma unroll
    for (int k0 = 0; k0 < 128; k0 += 16) {
        uint32_t a0 = 0, a1 = 0, a2 = 0, a3 = 0;
        if (okA) {
            a0 = *(const uint32_t*)&A[offA + k0];
            a2 = *(const uint32_t*)&A[offA + k0 + 8];
        }
        if (okB) {
            a1 = *(const uint32_t*)&A[offB + k0];
            a3 = *(const uint32_t*)&A[offB + k0 + 8];
        }
#pragma unroll
        for (int t = 0; t < NT; t++) {
            const __half* bp = &sB[(ncol0 + t * 8 + grp) * BS + k0 + qid * 2];
            uint32_t b0 = *(const uint32_t*)bp;
            uint32_t b1 = *(const uint32_t*)(bp + 8);
            mma_f16(acc[t], a0, a1, a2, a3, b0, b1);
        }
    }

    float dA = okA ? g_dinv[rowA] : 0.f;
    float dB = okB ? g_dinv[rowB] : 0.f;
#pragma unroll
    for (int t = 0; t < NT; t++) {
        int col = ncol0 + t * 8 + qid * 2;
        if (okA) *(__half2*)&Out[(size_t)rowA * 128 + col] =
            __floats2half2_rn(acc[t][0] * dA, acc[t][1] * dA);
        if (okB) *(__half2*)&Out[(size_t)rowB * 128 + col] =
            __floats2half2_rn(acc[t][2] * dB, acc[t][3] * dB);
    }
}

// [n,128] @ W2[K=128,40] -> dinv-prescaled fp16. CTA tile 128 x 40, 8 warps in M, NT=5.
__global__ void __launch_bounds__(256) k_gemm40(
    const __half* __restrict__ A, const __half* __restrict__ Bh,
    __half* __restrict__ Out, int n)
{
    constexpr int NT = ODIM / 8;
    constexpr int BS = 136;
    __shared__ __half sB[ODIM * BS];

    int tid = threadIdx.x, wid = tid >> 5, lane = tid & 31;
    int grp = lane >> 2;
    int qid = lane & 3;
    int rowA = blockIdx.x * 128 + wid * 16 + grp;
    int rowB = rowA + 8;
    bool okA = rowA < n, okB = rowB < n;

    for (int i = tid; i < ODIM * 16; i += 256) {
        int r = i >> 4, ck = i & 15;
        *(int4*)&sB[r * BS + ck * 8] = *(const int4*)&Bh[(size_t)r * 128 + ck * 8];
    }
    __syncthreads();

    float acc[NT][4];
#pragma unroll
    for (int t = 0; t < NT; t++)
#pragma unroll
        for (int j = 0; j < 4; j++) acc[t][j] = 0.f;

    const size_t offA = (size_t)rowA * 128 + qid * 2;
    const size_t offB = (size_t)rowB * 128 + qid * 2;

#pragma unroll
    for (int k0 = 0; k0 < 128; k0 += 16) {
        uint32_t a0 = 0, a1 = 0, a2 = 0, a3 = 0;
        if (okA) {
            a0 = *(const uint32_t*)&A[offA + k0];
            a2 = *(const uint32_t*)&A[offA + k0 + 8];
        }
        if (okB) {
            a1 = *(const uint32_t*)&A[offB + k0];
            a3 = *(const uint32_t*)&A[offB + k0 + 8];
        }
#pragma unroll
        for (int t = 0; t < NT; t++) {
            const __half* bp = &sB[(t * 8 + grp) * BS + k0 + qid * 2];
            uint32_t b0 = *(const uint32_t*)bp;
            uint32_t b1 = *(const uint32_t*)(bp + 8);
            mma_f16(acc[t], a0, a1, a2, a3, b0, b1);
        }
    }

    float dA = okA ? g_dinv[rowA] : 0.f;
    float dB = okB ? g_dinv[rowB] : 0.f;
#pragma unroll
    for (int t = 0; t < NT; t++) {
        int col = t * 8 + qid * 2;
        if (okA) *(__half2*)&Out[(size_t)rowA * ODIM + col] =
            __floats2half2_rn(acc[t][0] * dA, acc[t][1] * dA);
        if (okB) *(__half2*)&Out[(size_t)rowB * ODIM + col] =
            __floats2half2_rn(acc[t][2] * dB, acc[t][3] * dB);
    }
}

// ======================= aggregation (128-wide): unweighted gather-sum of h' =======================
__device__ __forceinline__ float4 ldrow128(const __half* __restrict__ H, int row, int lane) {
    uint2 u = *(const uint2*)&H[(size_t)row * 128 + lane * 4];
    float2 fa = __half22float2(*(__half2*)&u.x);
    float2 fb = __half22float2(*(__half2*)&u.y);
    return make_float4(fa.x, fa.y, fb.x, fb.y);
}

__global__ void __launch_bounds__(256) k_agg128(
    const __half* __restrict__ Hh, const float* __restrict__ b,
    __half* __restrict__ Oh, int n)
{
    int gw = (blockIdx.x * blockDim.x + threadIdx.x) >> 5;
    int lane = threadIdx.x & 31;
    if (gw >= n) return;

    // out = relu( dinv[d] * (h'_d + sum h'_s) + b ),  h' rows are dinv-prescaled
    float4 acc = ldrow128(Hh, gw, lane);   // self term h'_d

    int beg = g_rowptr[gw];
    int m = g_cnt[gw];
    int e = 0;
    for (; e + 3 < m; e += 4) {
        int s0 = __ldg(&g_esrc[beg + e]);
        int s1 = __ldg(&g_esrc[beg + e + 1]);
        int s2 = __ldg(&g_esrc[beg + e + 2]);
        int s3 = __ldg(&g_esrc[beg + e + 3]);
        float4 v0 = ldrow128(Hh, s0, lane);
        float4 v1 = ldrow128(Hh, s1, lane);
        float4 v2 = ldrow128(Hh, s2, lane);
        float4 v3 = ldrow128(Hh, s3, lane);
        acc.x += v0.x + v1.x + v2.x + v3.x;
        acc.y += v0.y + v1.y + v2.y + v3.y;
        acc.z += v0.z + v1.z + v2.z + v3.z;
        acc.w += v0.w + v1.w + v2.w + v3.w;
    }
    for (; e < m; e++) {
        int s0 = __ldg(&g_esrc[beg + e]);
        float4 v0 = ldrow128(Hh, s0, lane);
        acc.x += v0.x; acc.y += v0.y; acc.z += v0.z; acc.w += v0.w;
    }

    float dd = g_dinv[gw];
    float4 bb = *(const float4*)&b[lane * 4];
    acc.x = fmaxf(fmaf(acc.x, dd, bb.x), 0.f);
    acc.y = fmaxf(fmaf(acc.y, dd, bb.y), 0.f);
    acc.z = fmaxf(fmaf(acc.z, dd, bb.z), 0.f);
    acc.w = fmaxf(fmaf(acc.w, dd, bb.w), 0.f);

    __half2* ph = (__half2*)&Oh[(size_t)gw * 128 + lane * 4];
    ph[0] = __floats2half2_rn(acc.x, acc.y);
    ph[1] = __floats2half2_rn(acc.z, acc.w);
}

// ======================= aggregation (40-wide) + bias + ReLU + log_softmax =======================
__global__ void __launch_bounds__(256) k_agg40(
    const __half* __restrict__ H3, const float* __restrict__ b2,
    float* __restrict__ O, int n)
{
    int gw = (blockIdx.x * blockDim.x + threadIdx.x) >> 5;
    int lane = threadIdx.x & 31;
    if (gw >= n) return;

    const __half* hr = &H3[(size_t)gw * ODIM];
    float a1 = __half2float(hr[lane]);
    float a2 = (lane < 8) ? __half2float(hr[32 + lane]) : 0.f;

    int beg = g_rowptr[gw];
    int m = g_cnt[gw];
    int e = 0;
    for (; e + 1 < m; e += 2) {
        int s0 = __ldg(&g_esrc[beg + e]);
        int s1 = __ldg(&g_esrc[beg + e + 1]);
        const __half* r0 = &H3[(size_t)s0 * ODIM];
        const __half* r1 = &H3[(size_t)s1 * ODIM];
        a1 += __half2float(r0[lane]) + __half2float(r1[lane]);
        if (lane < 8)
            a2 += __half2float(r0[32 + lane]) + __half2float(r1[32 + lane]);
    }
    if (e < m) {
        int s = __ldg(&g_esrc[beg + e]);
        const __half* sr = &H3[(size_t)s * ODIM];
        a1 += __half2float(sr[lane]);
        if (lane < 8) a2 += __half2float(sr[32 + lane]);
    }

    float dd = g_dinv[gw];
    a1 = fmaxf(fmaf(a1, dd, b2[lane]), 0.f);
    if (lane < 8) a2 = fmaxf(fmaf(a2, dd, b2[32 + lane]), 0.f);

    float mx = fmaxf(a1, (lane < 8) ? a2 : -1e30f);
#pragma unroll
    for (int off = 16; off > 0; off >>= 1)
        mx = fmaxf(mx, __shfl_xor_sync(0xFFFFFFFFu, mx, off));

    float s = expf(a1 - mx) + ((lane < 8) ? expf(a2 - mx) : 0.f);
#pragma unroll
    for (int off = 16; off > 0; off >>= 1)
        s += __shfl_xor_sync(0xFFFFFFFFu, s, off);

    float l = mx + logf(s);
    O[(size_t)gw * ODIM + lane] = a1 - l;
    if (lane < 8) O[(size_t)gw * ODIM + 32 + lane] = a2 - l;
}

// ======================= launch (fork-join multi-stream capture) =======================
extern "C" void kernel_launch(void* const* d_in, const int* in_sizes, int n_in,
                              void* d_out, int out_size)
{
    const float* x  = (const float*)d_in[0];
    const void*  ei = d_in[1];
    const float* W0 = (const float*)d_in[2];
    const float* b0 = (const float*)d_in[3];
    const float* W1 = (const float*)d_in[4];
    const float* b1 = (const float*)d_in[5];
    const float* W2 = (const float*)d_in[6];
    const float* b2 = (const float*)d_in[7];
    float* out = (float*)d_out;

    int N = in_sizes[0] / HD;
    int E = in_sizes[1] / 2;

    __half *hhP, *xP, *aP, *w0h, *w1h, *w2h;
    cudaGetSymbolAddress((void**)&hhP, g_hh);
    cudaGetSymbolAddress((void**)&xP, g_x);
    cudaGetSymbolAddress((void**)&aP, g_a);
    cudaGetSymbolAddress((void**)&w0h, g_w0h);
    cudaGetSymbolAddress((void**)&w1h, g_w1h);
    cudaGetSymbolAddress((void**)&w2h, g_w2h);

    int tb = 256;
    int nbN = (N + tb - 1) / tb;
    int nbE = (E + tb - 1) / tb;
    int nbWarp = (N * 32 + tb - 1) / tb;
    int nbG64 = (N + 63) / 64;
    int nbG128 = (N + 127) / 128;
    int total4 = N * HD / 4;
    int nbPrep = (total4 + 32768 + ODIM * 128 + tb - 1) / tb;

    // Fork a non-blocking side stream for the CSR build; main (capture-origin)
    // stream runs prep + layer-1 GEMM concurrently. Created fresh per call
    // (no static caching); capture-legal fork-join via events.
    cudaStream_t s1;
    cudaStreamCreateWithFlags(&s1, cudaStreamNonBlocking);
    cudaEvent_t eFork, eDinv, eFill;
    cudaEventCreateWithFlags(&eFork, cudaEventDisableTiming);
    cudaEventCreateWithFlags(&eDinv, cudaEventDisableTiming);
    cudaEventCreateWithFlags(&eFill, cudaEventDisableTiming);

    // fork
    cudaEventRecord(eFork, 0);
    cudaStreamWaitEvent(s1, eFork, 0);

    // side stream: CSR build chain
    k_init<<<nbN, tb, 0, s1>>>(ei, N);
    k_hist<<<nbE, tb, 0, s1>>>(ei, E);
    k_rowptr<<<nbN, tb, 0, s1>>>(N);
    cudaEventRecord(eDinv, s1);            // dinv + rowptr/cursor ready
    k_fill<<<nbE, tb, 0, s1>>>(ei, E);
    cudaEventRecord(eFill, s1);            // CSR complete

    // main stream: prep runs concurrently with CSR build
    k_prep<<<nbPrep, tb>>>(x, W0, W1, W2, total4);
    // layer-1 GEMM needs prep + dinv only
    cudaStreamWaitEvent(0, eDinv, 0);
    k_gemm128<<<nbG64, 256>>>(xP, w0h, hhP, N);
    // aggregation needs the filled CSR (join)
    cudaStreamWaitEvent(0, eFill, 0);
    k_agg128<<<nbWarp, tb>>>(hhP, b0, aP, N);
    // layer 2
    k_gemm128<<<nbG64, 256>>>(aP, w1h, hhP, N);
    k_agg128<<<nbWarp, tb>>>(hhP, b1, aP, N);
    // layer 3
    k_gemm40<<<nbG128, 256>>>(aP, w2h, hhP, N);
    k_agg40<<<nbWarp, tb>>>(hhP, b2, out, N);
}

// round 13
// speedup vs baseline: 1.6165x; 1.0307x over previous
#include <cuda_runtime.h>
#include <cuda_fp16.h>
#include <cstdint>

#define NN 50000
#define EE 800000
#define HD 128
#define ODIM 40

// ---------------- scratch (static __device__, no allocations) ----------------
__device__ __align__(16) __half g_hh[NN * HD];   // GEMM outputs h' = dinv*h, fp16 (40-wide reuse L3)
__device__ __align__(16) __half g_x[NN * HD];    // input x fp16
__device__ __align__(16) __half g_a[NN * HD];    // post-agg activations fp16
__device__ __align__(16) __half g_w0h[HD * HD];
__device__ __align__(16) __half g_w1h[HD * HD];
__device__ __align__(16) __half g_w2h[ODIM * HD];
__device__ float g_dinv[NN];
__device__ int   g_cnt[NN];
__device__ int   g_rowptr[NN];
__device__ int   g_cursor[NN];
__device__ int   g_esrc[EE];                     // CSR: src index per edge (4B records)
__device__ int   g_total;
__device__ int   g_is64;

// ======================= edge-index dtype detection =======================
__device__ __forceinline__ int load_edge(const void* ei, int idx) {
    if (g_is64) return (int)((const long long*)ei)[idx];
    return ((const int*)ei)[idx];
}

// ======================= CSR build =======================
__global__ void k_init(const void* ei, int n) {
    int i = blockIdx.x * blockDim.x + threadIdx.x;
    if (i < n) g_cnt[i] = 0;
    if (i == 0) g_total = 0;
    if (blockIdx.x == 0) {
        __shared__ int any;
        if (threadIdx.x == 0) any = 0;
        __syncthreads();
        const int* p = (const int*)ei;
        for (int j = threadIdx.x; j < 512; j += blockDim.x)
            if (p[2 * j + 1] != 0) any = 1;
        __syncthreads();
        if (threadIdx.x == 0) g_is64 = any ? 0 : 1;
    }
}

// 4 edges per thread: 4 independent atomic chains in flight (latency-bound kernel)
__global__ void k_hist(const void* ei, int E) {
    int base = (blockIdx.x * blockDim.x + threadIdx.x) * 4;
    if (base >= E) return;
    if (base + 3 < E) {
        int d0 = load_edge(ei, E + base);
        int d1 = load_edge(ei, E + base + 1);
        int d2 = load_edge(ei, E + base + 2);
        int d3 = load_edge(ei, E + base + 3);
        atomicAdd(&g_cnt[d0], 1);
        atomicAdd(&g_cnt[d1], 1);
        atomicAdd(&g_cnt[d2], 1);
        atomicAdd(&g_cnt[d3], 1);
    } else {
        for (int e = base; e < E; e++)
            atomicAdd(&g_cnt[load_edge(ei, E + e)], 1);
    }
}

// unordered segment assignment (order irrelevant: fill uses cursors, agg uses rowptr+cnt)
__global__ void k_rowptr(int n) {
    int i = blockIdx.x * blockDim.x + threadIdx.x;
    if (i >= n) return;
    int c = g_cnt[i];
    g_dinv[i] = rsqrtf((float)(c + 1));
    int pos = atomicAdd(&g_total, c);
    g_rowptr[i] = pos;
    g_cursor[i] = pos;
}

// 4 edges per thread: 4 independent atomic->store chains in flight
__global__ void k_fill(const void* ei, int E) {
    int base = (blockIdx.x * blockDim.x + threadIdx.x) * 4;
    if (base >= E) return;
    if (base + 3 < E) {
        int s0 = load_edge(ei, base);
        int s1 = load_edge(ei, base + 1);
        int s2 = load_edge(ei, base + 2);
        int s3 = load_edge(ei, base + 3);
        int d0 = load_edge(ei, E + base);
        int d1 = load_edge(ei, E + base + 1);
        int d2 = load_edge(ei, E + base + 2);
        int d3 = load_edge(ei, E + base + 3);
        int p0 = atomicAdd(&g_cursor[d0], 1);
        int p1 = atomicAdd(&g_cursor[d1], 1);
        int p2 = atomicAdd(&g_cursor[d2], 1);
        int p3 = atomicAdd(&g_cursor[d3], 1);
        g_esrc[p0] = s0;
        g_esrc[p1] = s1;
        g_esrc[p2] = s2;
        g_esrc[p3] = s3;
    } else {
        for (int e = base; e < E; e++) {
            int s = load_edge(ei, e);
            int d = load_edge(ei, E + e);
            int pos = atomicAdd(&g_cursor[d], 1);
            g_esrc[pos] = s;
        }
    }
}

// ======================= prep: x -> fp16 + W transpose/quantize =======================
__global__ void k_prep(const float* __restrict__ x, const float* __restrict__ W0,
                       const float* __restrict__ W1, const float* __restrict__ W2,
                       int total4)
{
    int i = blockIdx.x * blockDim.x + threadIdx.x;
    if (i < total4) {
        float4 v = ((const float4*)x)[i];
        __half2* ph = (__half2*)&g_x[(size_t)i * 4];
        ph[0] = __halves2half2(__float2half_rn(v.x), __float2half_rn(v.y));
        ph[1] = __halves2half2(__float2half_rn(v.z), __float2half_rn(v.w));
    } else {
        int j = i - total4;
        if (j < 16384) {
            g_w0h[j] = __float2half_rn(W0[(j & 127) * 128 + (j >> 7)]);
        } else if (j < 32768) {
            int k = j - 16384;
            g_w1h[k] = __float2half_rn(W1[(k & 127) * 128 + (k >> 7)]);
        } else if (j < 32768 + ODIM * 128) {
            int k = j - 32768;
            int nn = k >> 7, kk = k & 127;
            g_w2h[k] = __float2half_rn(W2[kk * ODIM + nn]);
        }
    }
}

// ======================= mma.sync fp16 GEMM =======================
__device__ __forceinline__ void mma_f16(float* c, uint32_t a0, uint32_t a1,
                                        uint32_t a2, uint32_t a3,
                                        uint32_t b0, uint32_t b1) {
    asm volatile(
        "mma.sync.aligned.m16n8k16.row.col.f32.f16.f16.f32 "
        "{%0,%1,%2,%3}, {%4,%5,%6,%7}, {%8,%9}, {%0,%1,%2,%3};"
        : "+f"(c[0]), "+f"(c[1]), "+f"(c[2]), "+f"(c[3])
        : "r"(a0), "r"(a1), "r"(a2), "r"(a3), "r"(b0), "r"(b1));
}

// [n,128] @ W[K=128,128] -> h' = dinv[row] * (A@W), fp16 out (fp32 accum).
// CTA tile 64 x 128, 8 warps (4 M x 2 N), warp tile 16 x 64, NT=8.
__global__ void __launch_bounds__(256) k_gemm128(
    const __half* __restrict__ A, const __half* __restrict__ Bh,
    __half* __restrict__ Out, int n)
{
    constexpr int NT = 8;
    constexpr int BS = 136;
    __shared__ __half sB[HD * BS];

    int tid = threadIdx.x, wid = tid >> 5, lane = tid & 31;
    int widM = wid & 3, widN = wid >> 2;
    int grp = lane >> 2;
    int qid = lane & 3;
    int rowA = blockIdx.x * 64 + widM * 16 + grp;
    int rowB = rowA + 8;
    bool okA = rowA < n, okB = rowB < n;
    int ncol0 = widN * 64;

#pragma unroll
    for (int it = 0; it < 8; it++) {
        int i = it * 256 + tid;
        int r = i >> 4, ck = i & 15;
        *(int4*)&sB[r * BS + ck * 8] = *(const int4*)&Bh[(size_t)r * 128 + ck * 8];
    }
    __syncthreads();

    float acc[NT][4];
#pragma unroll
    for (int t = 0; t < NT; t++)
#pragma unroll
        for (int j = 0; j < 4; j++) acc[t][j] = 0.f;

    const size_t offA = (size_t)rowA * 128 + qid * 2;
    const size_t offB = (size_t)rowB * 128 + qid * 2;

#pragma unroll
    for (int k0 = 0; k0 < 128; k0 += 16) {
        uint32_t a0 = 0, a1 = 0, a2 = 0, a3 = 0;
        if (okA) {
            a0 = *(const uint32_t*)&A[offA + k0];
            a2 = *(const uint32_t*)&A[offA + k0 + 8];
        }
        if (okB) {
            a1 = *(const uint32_t*)&A[offB + k0];
            a3 = *(const uint32_t*)&A[offB + k0 + 8];
        }
#pragma unroll
        for (int t = 0; t < NT; t++) {
            const __half* bp = &sB[(ncol0 + t * 8 + grp) * BS + k0 + qid * 2];
            uint32_t b0 = *(const uint32_t*)bp;
            uint32_t b1 = *(const uint32_t*)(bp + 8);
            mma_f16(acc[t], a0, a1, a2, a3, b0, b1);
        }
    }

    float dA = okA ? g_dinv[rowA] : 0.f;
    float dB = okB ? g_dinv[rowB] : 0.f;
#pragma unroll
    for (int t = 0; t < NT; t++) {
        int col = ncol0 + t * 8 + qid * 2;
        if (okA) *(__half2*)&Out[(size_t)rowA * 128 + col] =
            __floats2half2_rn(acc[t][0] * dA, acc[t][1] * dA);
        if (okB) *(__half2*)&Out[(size_t)rowB * 128 + col] =
            __floats2half2_rn(acc[t][2] * dB, acc[t][3] * dB);
    }
}

// [n,128] @ W2[K=128,40] -> dinv-prescaled fp16. CTA tile 128 x 40, 8 warps in M, NT=5.
__global__ void __launch_bounds__(256) k_gemm40(
    const __half* __restrict__ A, const __half* __restrict__ Bh,
    __half* __restrict__ Out, int n)
{
    constexpr int NT = ODIM / 8;
    constexpr int BS = 136;
    __shared__ __half sB[ODIM * BS];

    int tid = threadIdx.x, wid = tid >> 5, lane = tid & 31;
    int grp = lane >> 2;
    int qid = lane & 3;
    int rowA = blockIdx.x * 128 + wid * 16 + grp;
    int rowB = rowA + 8;
    bool okA = rowA < n, okB = rowB < n;

    for (int i = tid; i < ODIM * 16; i += 256) {
        int r = i >> 4, ck = i & 15;
        *(int4*)&sB[r * BS + ck * 8] = *(const int4*)&Bh[(size_t)r * 128 + ck * 8];
    }
    __syncthreads();

    float acc[NT][4];
#pragma unroll
    for (int t = 0; t < NT; t++)
#pragma unroll
        for (int j = 0; j < 4; j++) acc[t][j] = 0.f;

    const size_t offA = (size_t)rowA * 128 + qid * 2;
    const size_t offB = (size_t)rowB * 128 + qid * 2;

#pragma unroll
    for (int k0 = 0; k0 < 128; k0 += 16) {
        uint32_t a0 = 0, a1 = 0, a2 = 0, a3 = 0;
        if (okA) {
            a0 = *(const uint32_t*)&A[offA + k0];
            a2 = *(const uint32_t*)&A[offA + k0 + 8];
        }
        if (okB) {
            a1 = *(const uint32_t*)&A[offB + k0];
            a3 = *(const uint32_t*)&A[offB + k0 + 8];
        }
#pragma unroll
        for (int t = 0; t < NT; t++) {
            const __half* bp = &sB[(t * 8 + grp) * BS + k0 + qid * 2];
            uint32_t b0 = *(const uint32_t*)bp;
            uint32_t b1 = *(const uint32_t*)(bp + 8);
            mma_f16(acc[t], a0, a1, a2, a3, b0, b1);
        }
    }

    float dA = okA ? g_dinv[rowA] : 0.f;
    float dB = okB ? g_dinv[rowB] : 0.f;
#pragma unroll
    for (int t = 0; t < NT; t++) {
        int col = t * 8 + qid * 2;
        if (okA) *(__half2*)&Out[(size_t)rowA * ODIM + col] =
            __floats2half2_rn(acc[t][0] * dA, acc[t][1] * dA);
        if (okB) *(__half2*)&Out[(size_t)rowB * ODIM + col] =
            __floats2half2_rn(acc[t][2] * dB, acc[t][3] * dB);
    }
}

// ======================= aggregation (128-wide): unweighted gather-sum of h' =======================
__device__ __forceinline__ float4 ldrow128(const __half* __restrict__ H, int row, int lane) {
    uint2 u = *(const uint2*)&H[(size_t)row * 128 + lane * 4];
    float2 fa = __half22float2(*(__half2*)&u.x);
    float2 fb = __half22float2(*(__half2*)&u.y);
    return make_float4(fa.x, fa.y, fb.x, fb.y);
}

__global__ void __launch_bounds__(256) k_agg128(
    const __half* __restrict__ Hh, const float* __restrict__ b,
    __half* __restrict__ Oh, int n)
{
    int gw = (blockIdx.x * blockDim.x + threadIdx.x) >> 5;
    int lane = threadIdx.x & 31;
    if (gw >= n) return;

    // out = relu( dinv[d] * (h'_d + sum h'_s) + b ),  h' rows are dinv-prescaled
    float4 acc = ldrow128(Hh, gw, lane);   // self term h'_d

    int beg = g_rowptr[gw];
    int m = g_cnt[gw];
    int e = 0;
    // 8-wide unroll: 16 outstanding loads per warp iteration
    for (; e + 7 < m; e += 8) {
        int s0 = __ldg(&g_esrc[beg + e]);
        int s1 = __ldg(&g_esrc[beg + e + 1]);
        int s2 = __ldg(&g_esrc[beg + e + 2]);
        int s3 = __ldg(&g_esrc[beg + e + 3]);
        int s4 = __ldg(&g_esrc[beg + e + 4]);
        int s5 = __ldg(&g_esrc[beg + e + 5]);
        int s6 = __ldg(&g_esrc[beg + e + 6]);
        int s7 = __ldg(&g_esrc[beg + e + 7]);
        float4 v0 = ldrow128(Hh, s0, lane);
        float4 v1 = ldrow128(Hh, s1, lane);
        float4 v2 = ldrow128(Hh, s2, lane);
        float4 v3 = ldrow128(Hh, s3, lane);
        float4 v4 = ldrow128(Hh, s4, lane);
        float4 v5 = ldrow128(Hh, s5, lane);
        float4 v6 = ldrow128(Hh, s6, lane);
        float4 v7 = ldrow128(Hh, s7, lane);
        acc.x += (v0.x + v1.x) + (v2.x + v3.x) + ((v4.x + v5.x) + (v6.x + v7.x));
        acc.y += (v0.y + v1.y) + (v2.y + v3.y) + ((v4.y + v5.y) + (v6.y + v7.y));
        acc.z += (v0.z + v1.z) + (v2.z + v3.z) + ((v4.z + v5.z) + (v6.z + v7.z));
        acc.w += (v0.w + v1.w) + (v2.w + v3.w) + ((v4.w + v5.w) + (v6.w + v7.w));
    }
    for (; e + 3 < m; e += 4) {
        int s0 = __ldg(&g_esrc[beg + e]);
        int s1 = __ldg(&g_esrc[beg + e + 1]);
        int s2 = __ldg(&g_esrc[beg + e + 2]);
        int s3 = __ldg(&g_esrc[beg + e + 3]);
        float4 v0 = ldrow128(Hh, s0, lane);
        float4 v1 = ldrow128(Hh, s1, lane);
        float4 v2 = ldrow128(Hh, s2, lane);
        float4 v3 = ldrow128(Hh, s3, lane);
        acc.x += (v0.x + v1.x) + (v2.x + v3.x);
        acc.y += (v0.y + v1.y) + (v2.y + v3.y);
        acc.z += (v0.z + v1.z) + (v2.z + v3.z);
        acc.w += (v0.w + v1.w) + (v2.w + v3.w);
    }
    for (; e < m; e++) {
        int s0 = __ldg(&g_esrc[beg + e]);
        float4 v0 = ldrow128(Hh, s0, lane);
        acc.x += v0.x; acc.y += v0.y; acc.z += v0.z; acc.w += v0.w;
    }

    float dd = g_dinv[gw];
    float4 bb = *(const float4*)&b[lane * 4];
    acc.x = fmaxf(fmaf(acc.x, dd, bb.x), 0.f);
    acc.y = fmaxf(fmaf(acc.y, dd, bb.y), 0.f);
    acc.z = fmaxf(fmaf(acc.z, dd, bb.z), 0.f);
    acc.w = fmaxf(fmaf(acc.w, dd, bb.w), 0.f);

    __half2* ph = (__half2*)&Oh[(size_t)gw * 128 + lane * 4];
    ph[0] = __floats2half2_rn(acc.x, acc.y);
    ph[1] = __floats2half2_rn(acc.z, acc.w);
}

// ======================= aggregation (40-wide) + bias + ReLU + log_softmax =======================
__global__ void __launch_bounds__(256) k_agg40(
    const __half* __restrict__ H3, const float* __restrict__ b2,
    float* __restrict__ O, int n)
{
    int gw = (blockIdx.x * blockDim.x + threadIdx.x) >> 5;
    int lane = threadIdx.x & 31;
    if (gw >= n) return;

    const __half* hr = &H3[(size_t)gw * ODIM];
    float a1 = __half2float(hr[lane]);
    float a2 = (lane < 8) ? __half2float(hr[32 + lane]) : 0.f;

    int beg = g_rowptr[gw];
    int m = g_cnt[gw];
    int e = 0;
    for (; e + 3 < m; e += 4) {
        int s0 = __ldg(&g_esrc[beg + e]);
        int s1 = __ldg(&g_esrc[beg + e + 1]);
        int s2 = __ldg(&g_esrc[beg + e + 2]);
        int s3 = __ldg(&g_esrc[beg + e + 3]);
        const __half* r0 = &H3[(size_t)s0 * ODIM];
        const __half* r1 = &H3[(size_t)s1 * ODIM];
        const __half* r2 = &H3[(size_t)s2 * ODIM];
        const __half* r3 = &H3[(size_t)s3 * ODIM];
        a1 += (__half2float(r0[lane]) + __half2float(r1[lane]))
            + (__half2float(r2[lane]) + __half2float(r3[lane]));
        if (lane < 8)
            a2 += (__half2float(r0[32 + lane]) + __half2float(r1[32 + lane]))
                + (__half2float(r2[32 + lane]) + __half2float(r3[32 + lane]));
    }
    for (; e < m; e++) {
        int s = __ldg(&g_esrc[beg + e]);
        const __half* sr = &H3[(size_t)s * ODIM];
        a1 += __half2float(sr[lane]);
        if (lane < 8) a2 += __half2float(sr[32 + lane]);
    }

    float dd = g_dinv[gw];
    a1 = fmaxf(fmaf(a1, dd, b2[lane]), 0.f);
    if (lane < 8) a2 = fmaxf(fmaf(a2, dd, b2[32 + lane]), 0.f);

    float mx = fmaxf(a1, (lane < 8) ? a2 : -1e30f);
#pragma unroll
    for (int off = 16; off > 0; off >>= 1)
        mx = fmaxf(mx, __shfl_xor_sync(0xFFFFFFFFu, mx, off));

    float s = expf(a1 - mx) + ((lane < 8) ? expf(a2 - mx) : 0.f);
#pragma unroll
    for (int off = 16; off > 0; off >>= 1)
        s += __shfl_xor_sync(0xFFFFFFFFu, s, off);

    float l = mx + logf(s);
    O[(size_t)gw * ODIM + lane] = a1 - l;
    if (lane < 8) O[(size_t)gw * ODIM + 32 + lane] = a2 - l;
}

// ======================= launch (fork-join multi-stream capture) =======================
extern "C" void kernel_launch(void* const* d_in, const int* in_sizes, int n_in,
                              void* d_out, int out_size)
{
    const float* x  = (const float*)d_in[0];
    const void*  ei = d_in[1];
    const float* W0 = (const float*)d_in[2];
    const float* b0 = (const float*)d_in[3];
    const float* W1 = (const float*)d_in[4];
    const float* b1 = (const float*)d_in[5];
    const float* W2 = (const float*)d_in[6];
    const float* b2 = (const float*)d_in[7];
    float* out = (float*)d_out;

    int N = in_sizes[0] / HD;
    int E = in_sizes[1] / 2;

    __half *hhP, *xP, *aP, *w0h, *w1h, *w2h;
    cudaGetSymbolAddress((void**)&hhP, g_hh);
    cudaGetSymbolAddress((void**)&xP, g_x);
    cudaGetSymbolAddress((void**)&aP, g_a);
    cudaGetSymbolAddress((void**)&w0h, g_w0h);
    cudaGetSymbolAddress((void**)&w1h, g_w1h);
    cudaGetSymbolAddress((void**)&w2h, g_w2h);

    int tb = 256;
    int nbN = (N + tb - 1) / tb;
    int nbE4 = (E + tb * 4 - 1) / (tb * 4);
    int nbWarp = (N * 32 + tb - 1) / tb;
    int nbG64 = (N + 63) / 64;
    int nbG128 = (N + 127) / 128;
    int total4 = N * HD / 4;
    int nbPrep = (total4 + 32768 + ODIM * 128 + tb - 1) / tb;

    cudaStream_t s1;
    cudaStreamCreateWithFlags(&s1, cudaStreamNonBlocking);
    cudaEvent_t eFork, eDinv, eFill;
    cudaEventCreateWithFlags(&eFork, cudaEventDisableTiming);
    cudaEventCreateWithFlags(&eDinv, cudaEventDisableTiming);
    cudaEventCreateWithFlags(&eFill, cudaEventDisableTiming);

    // fork
    cudaEventRecord(eFork, 0);
    cudaStreamWaitEvent(s1, eFork, 0);

    // side stream: CSR build chain (critical path — now ILP-unrolled)
    k_init<<<nbN, tb, 0, s1>>>(ei, N);
    k_hist<<<nbE4, tb, 0, s1>>>(ei, E);
    k_rowptr<<<nbN, tb, 0, s1>>>(N);
    cudaEventRecord(eDinv, s1);            // dinv + rowptr/cursor ready
    k_fill<<<nbE4, tb, 0, s1>>>(ei, E);
    cudaEventRecord(eFill, s1);            // CSR complete

    // main stream: prep runs concurrently with CSR build
    k_prep<<<nbPrep, tb>>>(x, W0, W1, W2, total4);
    // layer-1 GEMM needs prep + dinv only
    cudaStreamWaitEvent(0, eDinv, 0);
    k_gemm128<<<nbG64, 256>>>(xP, w0h, hhP, N);
    // aggregation needs the filled CSR (join)
    cudaStreamWaitEvent(0, eFill, 0);
    k_agg128<<<nbWarp, tb>>>(hhP, b0, aP, N);
    // layer 2
    k_gemm128<<<nbG64, 256>>>(aP, w1h, hhP, N);
    k_agg128<<<nbWarp, tb>>>(hhP, b1, aP, N);
    // layer 3
    k_gemm40<<<nbG128, 256>>>(aP, w2h, hhP, N);
    k_agg40<<<nbWarp, tb>>>(hhP, b2, out, N);
}

// round 15
// speedup vs baseline: 1.7439x; 1.0788x over previous
#include <cuda_runtime.h>
#include <cuda_fp16.h>
#include <cstdint>

#define NN 50000
#define EE 800000
#define HD 128
#define ODIM 40

// ---------------- scratch (static __device__, no allocations) ----------------
__device__ __align__(16) __half g_hh[NN * HD];   // GEMM outputs h' = dinv*h, fp16 (40-wide reuse L3)
__device__ __align__(16) __half g_x[NN * HD];    // input x fp16
__device__ __align__(16) __half g_a[NN * HD];    // post-agg activations fp16
__device__ __align__(16) __half g_w0h[HD * HD];
__device__ __align__(16) __half g_w1h[HD * HD];
__device__ __align__(16) __half g_w2h[ODIM * HD];
__device__ float g_dinv[NN];
__device__ int   g_cnt[NN];
__device__ int   g_rowptr[NN];
__device__ int   g_cursor[NN];
__device__ int   g_esrc[EE];                     // CSR: src index per edge (4B records)
__device__ int   g_total;
__device__ int   g_is64;

// ======================= edge-index dtype detection =======================
__device__ __forceinline__ int load_edge(const void* ei, int idx) {
    if (g_is64) return (int)((const long long*)ei)[idx];
    return ((const int*)ei)[idx];
}

// ======================= CSR build =======================
__global__ void k_init(const void* ei, int n) {
    int i = blockIdx.x * blockDim.x + threadIdx.x;
    if (i < n) g_cnt[i] = 0;
    if (i == 0) g_total = 0;
    if (blockIdx.x == 0) {
        __shared__ int any;
        if (threadIdx.x == 0) any = 0;
        __syncthreads();
        const int* p = (const int*)ei;
        for (int j = threadIdx.x; j < 512; j += blockDim.x)
            if (p[2 * j + 1] != 0) any = 1;
        __syncthreads();
        if (threadIdx.x == 0) g_is64 = any ? 0 : 1;
    }
}

// 4 edges per thread: independent atomic chains in flight
__global__ void k_hist(const void* ei, int E) {
    int base = (blockIdx.x * blockDim.x + threadIdx.x) * 4;
    if (base >= E) return;
    if (base + 3 < E) {
        int d0 = load_edge(ei, E + base);
        int d1 = load_edge(ei, E + base + 1);
        int d2 = load_edge(ei, E + base + 2);
        int d3 = load_edge(ei, E + base + 3);
        atomicAdd(&g_cnt[d0], 1);
        atomicAdd(&g_cnt[d1], 1);
        atomicAdd(&g_cnt[d2], 1);
        atomicAdd(&g_cnt[d3], 1);
    } else {
        for (int e = base; e < E; e++)
            atomicAdd(&g_cnt[load_edge(ei, E + e)], 1);
    }
}

// unordered segment assignment (order irrelevant: fill uses cursors, agg uses rowptr+cnt)
__global__ void k_rowptr(int n) {
    int i = blockIdx.x * blockDim.x + threadIdx.x;
    if (i >= n) return;
    int c = g_cnt[i];
    g_dinv[i] = rsqrtf((float)(c + 1));
    int pos = atomicAdd(&g_total, c);
    g_rowptr[i] = pos;
    g_cursor[i] = pos;
}

__global__ void k_fill(const void* ei, int E) {
    int base = (blockIdx.x * blockDim.x + threadIdx.x) * 4;
    if (base >= E) return;
    if (base + 3 < E) {
        int s0 = load_edge(ei, base);
        int s1 = load_edge(ei, base + 1);
        int s2 = load_edge(ei, base + 2);
        int s3 = load_edge(ei, base + 3);
        int d0 = load_edge(ei, E + base);
        int d1 = load_edge(ei, E + base + 1);
        int d2 = load_edge(ei, E + base + 2);
        int d3 = load_edge(ei, E + base + 3);
        int p0 = atomicAdd(&g_cursor[d0], 1);
        int p1 = atomicAdd(&g_cursor[d1], 1);
        int p2 = atomicAdd(&g_cursor[d2], 1);
        int p3 = atomicAdd(&g_cursor[d3], 1);
        g_esrc[p0] = s0;
        g_esrc[p1] = s1;
        g_esrc[p2] = s2;
        g_esrc[p3] = s3;
    } else {
        for (int e = base; e < E; e++) {
            int s = load_edge(ei, e);
            int d = load_edge(ei, E + e);
            int pos = atomicAdd(&g_cursor[d], 1);
            g_esrc[pos] = s;
        }
    }
}

// ======================= prep: x -> fp16 + W transpose/quantize =======================
__global__ void k_prep(const float* __restrict__ x, const float* __restrict__ W0,
                       const float* __restrict__ W1, const float* __restrict__ W2,
                       int total4)
{
    int i = blockIdx.x * blockDim.x + threadIdx.x;
    if (i < total4) {
        float4 v = ((const float4*)x)[i];
        __half2* ph = (__half2*)&g_x[(size_t)i * 4];
        ph[0] = __halves2half2(__float2half_rn(v.x), __float2half_rn(v.y));
        ph[1] = __halves2half2(__float2half_rn(v.z), __float2half_rn(v.w));
    } else {
        int j = i - total4;
        if (j < 16384) {
            g_w0h[j] = __float2half_rn(W0[(j & 127) * 128 + (j >> 7)]);
        } else if (j < 32768) {
            int k = j - 16384;
            g_w1h[k] = __float2half_rn(W1[(k & 127) * 128 + (k >> 7)]);
        } else if (j < 32768 + ODIM * 128) {
            int k = j - 32768;
            int nn = k >> 7, kk = k & 127;
            g_w2h[k] = __float2half_rn(W2[kk * ODIM + nn]);
        }
    }
}

// ======================= mma.sync fp16 GEMM =======================
__device__ __forceinline__ void mma_f16(float* c, uint32_t a0, uint32_t a1,
                                        uint32_t a2, uint32_t a3,
                                        uint32_t b0, uint32_t b1) {
    asm volatile(
        "mma.sync.aligned.m16n8k16.row.col.f32.f16.f16.f32 "
        "{%0,%1,%2,%3}, {%4,%5,%6,%7}, {%8,%9}, {%0,%1,%2,%3};"
        : "+f"(c[0]), "+f"(c[1]), "+f"(c[2]), "+f"(c[3])
        : "r"(a0), "r"(a1), "r"(a2), "r"(a3), "r"(b0), "r"(b1));
}

// [n,128] @ W[K=128,128] -> h' = dinv[row] * (A@W), fp16 out (fp32 accum).
// CTA tile 64 x 128, 8 warps (4 M x 2 N). A staged in smem (coalesced int4 loads,
// conflict-free 136-half stride), W staged in smem. Dynamic smem: 52224 B.
__global__ void __launch_bounds__(256) k_gemm128(
    const __half* __restrict__ A, const __half* __restrict__ Bh,
    __half* __restrict__ Out, int n)
{
    constexpr int NT = 8;
    constexpr int BS = 136;
    extern __shared__ __half smem[];
    __half* sA = smem;             // 64 x BS
    __half* sB = smem + 64 * BS;   // 128 x BS

    int tid = threadIdx.x, wid = tid >> 5, lane = tid & 31;
    int widM = wid & 3, widN = wid >> 2;
    int grp = lane >> 2;
    int qid = lane & 3;
    int row0 = blockIdx.x * 64;
    int rowA = row0 + widM * 16 + grp;
    int rowB = rowA + 8;
    bool okA = rowA < n, okB = rowB < n;
    int ncol0 = widN * 64;

    // stage A: 64 rows x 16 int4-chunks, coalesced, zero-padded past n
#pragma unroll
    for (int it = 0; it < 4; it++) {
        int i = it * 256 + tid;
        int r = i >> 4, ck = i & 15;
        int grow = row0 + r;
        int4 v = (grow < n) ? *(const int4*)&A[(size_t)grow * 128 + ck * 8]
                            : make_int4(0, 0, 0, 0);
        *(int4*)&sA[r * BS + ck * 8] = v;
    }
    // stage W: 128 rows x 16 int4-chunks
#pragma unroll
    for (int it = 0; it < 8; it++) {
        int i = it * 256 + tid;
        int r = i >> 4, ck = i & 15;
        *(int4*)&sB[r * BS + ck * 8] = *(const int4*)&Bh[(size_t)r * 128 + ck * 8];
    }
    __syncthreads();

    float acc[NT][4];
#pragma unroll
    for (int t = 0; t < NT; t++)
#pragma unroll
        for (int j = 0; j < 4; j++) acc[t][j] = 0.f;

    int arow = widM * 16 + grp;
    const __half* apL = &sA[arow * BS + qid * 2];
    const __half* apH = &sA[(arow + 8) * BS + qid * 2];

#pragma unroll
    for (int k0 = 0; k0 < 128; k0 += 16) {
        uint32_t a0 = *(const uint32_t*)(apL + k0);
        uint32_t a1 = *(const uint32_t*)(apH + k0);
        uint32_t a2 = *(const uint32_t*)(apL + k0 + 8);
        uint32_t a3 = *(const uint32_t*)(apH + k0 + 8);
#pragma unroll
        for (int t = 0; t < NT; t++) {
            const __half* bp = &sB[(ncol0 + t * 8 + grp) * BS + k0 + qid * 2];
            uint32_t b0 = *(const uint32_t*)bp;
            uint32_t b1 = *(const uint32_t*)(bp + 8);
            mma_f16(acc[t], a0, a1, a2, a3, b0, b1);
        }
    }

    float dA = okA ? g_dinv[rowA] : 0.f;
    float dB = okB ? g_dinv[rowB] : 0.f;
#pragma unroll
    for (int t = 0; t < NT; t++) {
        int col = ncol0 + t * 8 + qid * 2;
        if (okA) *(__half2*)&Out[(size_t)rowA * 128 + col] =
            __floats2half2_rn(acc[t][0] * dA, acc[t][1] * dA);
        if (okB) *(__half2*)&Out[(size_t)rowB * 128 + col] =
            __floats2half2_rn(acc[t][2] * dB, acc[t][3] * dB);
    }
}

// [n,128] @ W2[K=128,40] -> dinv-prescaled fp16. CTA tile 128 x 40, 8 warps in M.
// A staged in smem (static: 34816 + 10880 = 45696 B).
__global__ void __launch_bounds__(256) k_gemm40(
    const __half* __restrict__ A, const __half* __restrict__ Bh,
    __half* __restrict__ Out, int n)
{
    constexpr int NT = ODIM / 8;
    constexpr int BS = 136;
    __shared__ __half sA[128 * BS];
    __shared__ __half sB[ODIM * BS];

    int tid = threadIdx.x, wid = tid >> 5, lane = tid & 31;
    int grp = lane >> 2;
    int qid = lane & 3;
    int row0 = blockIdx.x * 128;
    int rowA = row0 + wid * 16 + grp;
    int rowB = rowA + 8;
    bool okA = rowA < n, okB = rowB < n;

    // stage A: 128 rows x 16 chunks
#pragma unroll
    for (int it = 0; it < 8; it++) {
        int i = it * 256 + tid;
        int r = i >> 4, ck = i & 15;
        int grow = row0 + r;
        int4 v = (grow < n) ? *(const int4*)&A[(size_t)grow * 128 + ck * 8]
                            : make_int4(0, 0, 0, 0);
        *(int4*)&sA[r * BS + ck * 8] = v;
    }
    for (int i = tid; i < ODIM * 16; i += 256) {
        int r = i >> 4, ck = i & 15;
        *(int4*)&sB[r * BS + ck * 8] = *(const int4*)&Bh[(size_t)r * 128 + ck * 8];
    }
    __syncthreads();

    float acc[NT][4];
#pragma unroll
    for (int t = 0; t < NT; t++)
#pragma unroll
        for (int j = 0; j < 4; j++) acc[t][j] = 0.f;

    int arow = wid * 16 + grp;
    const __half* apL = &sA[arow * BS + qid * 2];
    const __half* apH = &sA[(arow + 8) * BS + qid * 2];

#pragma unroll
    for (int k0 = 0; k0 < 128; k0 += 16) {
        uint32_t a0 = *(const uint32_t*)(apL + k0);
        uint32_t a1 = *(const uint32_t*)(apH + k0);
        uint32_t a2 = *(const uint32_t*)(apL + k0 + 8);
        uint32_t a3 = *(const uint32_t*)(apH + k0 + 8);
#pragma unroll
        for (int t = 0; t < NT; t++) {
            const __half* bp = &sB[(t * 8 + grp) * BS + k0 + qid * 2];
            uint32_t b0 = *(const uint32_t*)bp;
            uint32_t b1 = *(const uint32_t*)(bp + 8);
            mma_f16(acc[t], a0, a1, a2, a3, b0, b1);
        }
    }

    float dA = okA ? g_dinv[rowA] : 0.f;
    float dB = okB ? g_dinv[rowB] : 0.f;
#pragma unroll
    for (int t = 0; t < NT; t++) {
        int col = t * 8 + qid * 2;
        if (okA) *(__half2*)&Out[(size_t)rowA * ODIM + col] =
            __floats2half2_rn(acc[t][0] * dA, acc[t][1] * dA);
        if (okB) *(__half2*)&Out[(size_t)rowB * ODIM + col] =
            __floats2half2_rn(acc[t][2] * dB, acc[t][3] * dB);
    }
}

// ======================= aggregation (128-wide): unweighted gather-sum of h' =======================
__device__ __forceinline__ float4 ldrow128(const __half* __restrict__ H, int row, int lane) {
    uint2 u = *(const uint2*)&H[(size_t)row * 128 + lane * 4];
    float2 fa = __half22float2(*(__half2*)&u.x);
    float2 fb = __half22float2(*(__half2*)&u.y);
    return make_float4(fa.x, fa.y, fb.x, fb.y);
}

__global__ void __launch_bounds__(256) k_agg128(
    const __half* __restrict__ Hh, const float* __restrict__ b,
    __half* __restrict__ Oh, int n)
{
    int gw = (blockIdx.x * blockDim.x + threadIdx.x) >> 5;
    int lane = threadIdx.x & 31;
    if (gw >= n) return;

    // out = relu( dinv[d] * (h'_d + sum h'_s) + b ),  h' rows are dinv-prescaled
    float4 acc = ldrow128(Hh, gw, lane);   // self term h'_d

    int beg = g_rowptr[gw];
    int m = g_cnt[gw];
    int e = 0;
    for (; e + 7 < m; e += 8) {
        int s0 = __ldg(&g_esrc[beg + e]);
        int s1 = __ldg(&g_esrc[beg + e + 1]);
        int s2 = __ldg(&g_esrc[beg + e + 2]);
        int s3 = __ldg(&g_esrc[beg + e + 3]);
        int s4 = __ldg(&g_esrc[beg + e + 4]);
        int s5 = __ldg(&g_esrc[beg + e + 5]);
        int s6 = __ldg(&g_esrc[beg + e + 6]);
        int s7 = __ldg(&g_esrc[beg + e + 7]);
        float4 v0 = ldrow128(Hh, s0, lane);
        float4 v1 = ldrow128(Hh, s1, lane);
        float4 v2 = ldrow128(Hh, s2, lane);
        float4 v3 = ldrow128(Hh, s3, lane);
        float4 v4 = ldrow128(Hh, s4, lane);
        float4 v5 = ldrow128(Hh, s5, lane);
        float4 v6 = ldrow128(Hh, s6, lane);
        float4 v7 = ldrow128(Hh, s7, lane);
        acc.x += (v0.x + v1.x) + (v2.x + v3.x) + ((v4.x + v5.x) + (v6.x + v7.x));
        acc.y += (v0.y + v1.y) + (v2.y + v3.y) + ((v4.y + v5.y) + (v6.y + v7.y));
        acc.z += (v0.z + v1.z) + (v2.z + v3.z) + ((v4.z + v5.z) + (v6.z + v7.z));
        acc.w += (v0.w + v1.w) + (v2.w + v3.w) + ((v4.w + v5.w) + (v6.w + v7.w));
    }
    for (; e + 3 < m; e += 4) {
        int s0 = __ldg(&g_esrc[beg + e]);
        int s1 = __ldg(&g_esrc[beg + e + 1]);
        int s2 = __ldg(&g_esrc[beg + e + 2]);
        int s3 = __ldg(&g_esrc[beg + e + 3]);
        float4 v0 = ldrow128(Hh, s0, lane);
        float4 v1 = ldrow128(Hh, s1, lane);
        float4 v2 = ldrow128(Hh, s2, lane);
        float4 v3 = ldrow128(Hh, s3, lane);
        acc.x += (v0.x + v1.x) + (v2.x + v3.x);
        acc.y += (v0.y + v1.y) + (v2.y + v3.y);
        acc.z += (v0.z + v1.z) + (v2.z + v3.z);
        acc.w += (v0.w + v1.w) + (v2.w + v3.w);
    }
    for (; e < m; e++) {
        int s0 = __ldg(&g_esrc[beg + e]);
        float4 v0 = ldrow128(Hh, s0, lane);
        acc.x += v0.x; acc.y += v0.y; acc.z += v0.z; acc.w += v0.w;
    }

    float dd = g_dinv[gw];
    float4 bb = *(const float4*)&b[lane * 4];
    acc.x = fmaxf(fmaf(acc.x, dd, bb.x), 0.f);
    acc.y = fmaxf(fmaf(acc.y, dd, bb.y), 0.f);
    acc.z = fmaxf(fmaf(acc.z, dd, bb.z), 0.f);
    acc.w = fmaxf(fmaf(acc.w, dd, bb.w), 0.f);

    __half2* ph = (__half2*)&Oh[(size_t)gw * 128 + lane * 4];
    ph[0] = __floats2half2_rn(acc.x, acc.y);
    ph[1] = __floats2half2_rn(acc.z, acc.w);
}

// ======================= aggregation (40-wide) + bias + ReLU + log_softmax =======================
__global__ void __launch_bounds__(256) k_agg40(
    const __half* __restrict__ H3, const float* __restrict__ b2,
    float* __restrict__ O, int n)
{
    int gw = (blockIdx.x * blockDim.x + threadIdx.x) >> 5;
    int lane = threadIdx.x & 31;
    if (gw >= n) return;

    const __half* hr = &H3[(size_t)gw * ODIM];
    float a1 = __half2float(hr[lane]);
    float a2 = (lane < 8) ? __half2float(hr[32 + lane]) : 0.f;

    int beg = g_rowptr[gw];
    int m = g_cnt[gw];
    int e = 0;
    for (; e + 3 < m; e += 4) {
        int s0 = __ldg(&g_esrc[beg + e]);
        int s1 = __ldg(&g_esrc[beg + e + 1]);
        int s2 = __ldg(&g_esrc[beg + e + 2]);
        int s3 = __ldg(&g_esrc[beg + e + 3]);
        const __half* r0 = &H3[(size_t)s0 * ODIM];
        const __half* r1 = &H3[(size_t)s1 * ODIM];
        const __half* r2 = &H3[(size_t)s2 * ODIM];
        const __half* r3 = &H3[(size_t)s3 * ODIM];
        a1 += (__half2float(r0[lane]) + __half2float(r1[lane]))
            + (__half2float(r2[lane]) + __half2float(r3[lane]));
        if (lane < 8)
            a2 += (__half2float(r0[32 + lane]) + __half2float(r1[32 + lane]))
                + (__half2float(r2[32 + lane]) + __half2float(r3[32 + lane]));
    }
    for (; e < m; e++) {
        int s = __ldg(&g_esrc[beg + e]);
        const __half* sr = &H3[(size_t)s * ODIM];
        a1 += __half2float(sr[lane]);
        if (lane < 8) a2 += __half2float(sr[32 + lane]);
    }

    float dd = g_dinv[gw];
    a1 = fmaxf(fmaf(a1, dd, b2[lane]), 0.f);
    if (lane < 8) a2 = fmaxf(fmaf(a2, dd, b2[32 + lane]), 0.f);

    float mx = fmaxf(a1, (lane < 8) ? a2 : -1e30f);
#pragma unroll
    for (int off = 16; off > 0; off >>= 1)
        mx = fmaxf(mx, __shfl_xor_sync(0xFFFFFFFFu, mx, off));

    float s = expf(a1 - mx) + ((lane < 8) ? expf(a2 - mx) : 0.f);
#pragma unroll
    for (int off = 16; off > 0; off >>= 1)
        s += __shfl_xor_sync(0xFFFFFFFFu, s, off);

    float l = mx + logf(s);
    O[(size_t)gw * ODIM + lane] = a1 - l;
    if (lane < 8) O[(size_t)gw * ODIM + 32 + lane] = a2 - l;
}

// ======================= launch (fork-join multi-stream capture) =======================
extern "C" void kernel_launch(void* const* d_in, const int* in_sizes, int n_in,
                              void* d_out, int out_size)
{
    const float* x  = (const float*)d_in[0];
    const void*  ei = d_in[1];
    const float* W0 = (const float*)d_in[2];
    const float* b0 = (const float*)d_in[3];
    const float* W1 = (const float*)d_in[4];
    const float* b1 = (const float*)d_in[5];
    const float* W2 = (const float*)d_in[6];
    const float* b2 = (const float*)d_in[7];
    float* out = (float*)d_out;

    int N = in_sizes[0] / HD;
    int E = in_sizes[1] / 2;

    __half *hhP, *xP, *aP, *w0h, *w1h, *w2h;
    cudaGetSymbolAddress((void**)&hhP, g_hh);
    cudaGetSymbolAddress((void**)&xP, g_x);
    cudaGetSymbolAddress((void**)&aP, g_a);
    cudaGetSymbolAddress((void**)&w0h, g_w0h);
    cudaGetSymbolAddress((void**)&w1h, g_w1h);
    cudaGetSymbolAddress((void**)&w2h, g_w2h);

    const int SMG128 = (64 + 128) * 136 * (int)sizeof(__half);   // 52224
    cudaFuncSetAttribute(k_gemm128, cudaFuncAttributeMaxDynamicSharedMemorySize, SMG128);

    int tb = 256;
    int nbN = (N + tb - 1) / tb;
    int nbE4 = (E + tb * 4 - 1) / (tb * 4);
    int nbWarp = (N * 32 + tb - 1) / tb;
    int nbG64 = (N + 63) / 64;
    int nbG128 = (N + 127) / 128;
    int total4 = N * HD / 4;
    int nbPrep = (total4 + 32768 + ODIM * 128 + tb - 1) / tb;

    cudaStream_t s1;
    cudaStreamCreateWithFlags(&s1, cudaStreamNonBlocking);
    cudaEvent_t eFork, eDinv, eFill;
    cudaEventCreateWithFlags(&eFork, cudaEventDisableTiming);
    cudaEventCreateWithFlags(&eDinv, cudaEventDisableTiming);
    cudaEventCreateWithFlags(&eFill, cudaEventDisableTiming);

    // fork
    cudaEventRecord(eFork, 0);
    cudaStreamWaitEvent(s1, eFork, 0);

    // side stream: CSR build chain
    k_init<<<nbN, tb, 0, s1>>>(ei, N);
    k_hist<<<nbE4, tb, 0, s1>>>(ei, E);
    k_rowptr<<<nbN, tb, 0, s1>>>(N);
    cudaEventRecord(eDinv, s1);            // dinv + rowptr/cursor ready
    k_fill<<<nbE4, tb, 0, s1>>>(ei, E);
    cudaEventRecord(eFill, s1);            // CSR complete

    // main stream: prep runs concurrently with CSR build
    k_prep<<<nbPrep, tb>>>(x, W0, W1, W2, total4);
    // layer-1 GEMM needs prep + dinv only
    cudaStreamWaitEvent(0, eDinv, 0);
    k_gemm128<<<nbG64, 256, SMG128>>>(xP, w0h, hhP, N);
    // aggregation needs the filled CSR (join)
    cudaStreamWaitEvent(0, eFill, 0);
    k_agg128<<<nbWarp, tb>>>(hhP, b0, aP, N);
    // layer 2
    k_gemm128<<<nbG64, 256, SMG128>>>(aP, w1h, hhP, N);
    k_agg128<<<nbWarp, tb>>>(hhP, b1, aP, N);
    // layer 3
    k_gemm40<<<nbG128, 256>>>(aP, w2h, hhP, N);
    k_agg40<<<nbWarp, tb>>>(hhP, b2, out, N);
}